// round 11
// baseline (speedup 1.0000x reference)
#include <cuda_runtime.h>
#include <cuda_bf16.h>
#include <cstdint>
#include <math.h>

// Problem constants
#define IN_DIM 44
#define H      128
#define H4     512
#define NL     4
#define TDEC   50
#define BATCH  2048
#define SEQ    200

#define TBS 16                       // batch tile stride (smem layout)
#define TBU 14                       // batch rows actually used per block
#define RBLK ((BATCH + TBU - 1) / TBU)   // 147 recurrent/decoder blocks
#define NROWS (SEQ * BATCH)          // 409600 GEMM rows
#define MT64  (NROWS / 64)           // 6400 m-tiles
#define GBX   74                     // GEMM persistent blocks per N-half

typedef unsigned long long ull;
typedef __nv_bfloat16 bf16;

// ---------------------------------------------------------------------------
// Device scratch
// ---------------------------------------------------------------------------
__device__ float g_Xg[(long)NROWS * H4];        // gate-interleaved: [row][4c+g]
__device__ bf16  g_ysH[(long)NROWS * H];        // layer output hi plane [row][k]
__device__ bf16  g_ysL[(long)NROWS * H];        // layer output lo plane
__device__ bf16  g_x0H[(long)NROWS * 48];       // gathered x hi plane [row][48]
__device__ bf16  g_x0L[(long)NROWS * 48];
__device__ float g_h[NL * BATCH * H];
__device__ float g_c[NL * BATCH * H];
// permuted biases [l][4c+g]
__device__ float g_encBP[NL * H4];
__device__ float g_decBP[NL * H4];
// gate-grouped packed recurrent/input weights: float4[k*128+c] = {Wi,Wf,Wg,Wo}[c][k]
__device__ float g_encWhhP4[NL * H * H * 4];
__device__ float g_decWhhP4[NL * H * H * 4];
__device__ float g_decWihRP4[3 * H * H * 4];
__device__ float g_decWih0P4[IN_DIM * H * 4];
__device__ float g_fcT[H * IN_DIM];
// bf16 hi/lo GEMM weight planes, gate-permuted [n][k] (k padded)
__device__ bf16 g_W0H[512 * 48];
__device__ bf16 g_W0L[512 * 48];
__device__ bf16 g_WRH[3 * 512 * 128];
__device__ bf16 g_WRL[3 * 512 * 128];

// ---------------------------------------------------------------------------
// packed f32x2 helpers
// ---------------------------------------------------------------------------
__device__ __forceinline__ ull pack2(float a, float b) {
    ull r; asm("mov.b64 %0, {%1,%2};" : "=l"(r) : "f"(a), "f"(b)); return r;
}
__device__ __forceinline__ void unpack2(ull v, float& a, float& b) {
    asm("mov.b64 {%0,%1}, %2;" : "=f"(a), "=f"(b) : "l"(v));
}
__device__ __forceinline__ void ffma2(ull& d, ull a, ull b) {
    asm("fma.rn.f32x2 %0, %1, %2, %0;" : "+l"(d) : "l"(a), "l"(b));
}

// activations via MUFU.TANH
__device__ __forceinline__ float tanha(float x) {
    float y; asm("tanh.approx.f32 %0, %1;" : "=f"(y) : "f"(x)); return y;
}
__device__ __forceinline__ float sigf(float x) {
    return 0.5f * tanha(0.5f * x) + 0.5f;
}

// cp.async helpers
__device__ __forceinline__ void cp16(unsigned int dst, const void* src) {
    asm volatile("cp.async.ca.shared.global [%0], [%1], 16;"
                 :: "r"(dst), "l"(src));
}
__device__ __forceinline__ void cp_commit() {
    asm volatile("cp.async.commit_group;");
}
__device__ __forceinline__ void cp_wait0() {
    asm volatile("cp.async.wait_group 0;");
}

// bf16 mma m16n8k16, f32 accum (HMMA path — works on plain sm_103)
#define MMA_BF16(d, a, b)                                                     \
    asm volatile(                                                             \
        "mma.sync.aligned.m16n8k16.row.col.f32.bf16.bf16.f32 "                \
        "{%0,%1,%2,%3}, {%4,%5,%6,%7}, {%8,%9}, {%0,%1,%2,%3};"               \
        : "+f"((d)[0]), "+f"((d)[1]), "+f"((d)[2]), "+f"((d)[3])              \
        : "r"((a)[0]), "r"((a)[1]), "r"((a)[2]), "r"((a)[3]),                 \
          "r"((b)[0]), "r"((b)[1]))

#define LDSM4(r, addr)                                                        \
    asm volatile("ldmatrix.sync.aligned.m8n8.x4.shared.b16 "                  \
        "{%0,%1,%2,%3}, [%4];"                                                \
        : "=r"((r)[0]), "=r"((r)[1]), "=r"((r)[2]), "=r"((r)[3])              \
        : "r"(addr))

__device__ __forceinline__ void split_bf16(float v, bf16& h, bf16& l) {
    h = __float2bfloat16_rn(v);
    l = __float2bfloat16_rn(v - __bfloat162float(h));
}

// ---------------------------------------------------------------------------
// Prep kernel 1: gate-grouped 4-pack for recurrent kernels
// ---------------------------------------------------------------------------
struct GPJob { const float* s; float* d; int K; };
struct GPJobs { GPJob j[12]; int n; };

__global__ void k_pack4g(GPJobs jobs) {
    int job = blockIdx.y;
    if (job >= jobs.n) return;
    GPJob J = jobs.j[job];
    int i = blockIdx.x * 128 + threadIdx.x;
    if (i < J.K * 128) {
        int k = i >> 7, c = i & 127;
        float4 v;
        v.x = J.s[c * J.K + k];
        v.y = J.s[(128 + c) * J.K + k];
        v.z = J.s[(256 + c) * J.K + k];
        v.w = J.s[(384 + c) * J.K + k];
        ((float4*)J.d)[i] = v;
    }
}

// ---------------------------------------------------------------------------
// Prep kernel 2 (merged): biases/fcT + GEMM weight hi/lo planes
// grid.y: 0 = misc; 1 = W0; 2..4 = WR layers
// ---------------------------------------------------------------------------
__global__ void k_wconv(const float* __restrict__ enc_b, const float* __restrict__ dec_b,
                        const float* __restrict__ fc_W,
                        const float* __restrict__ Wih0, const float* __restrict__ WihR,
                        float* __restrict__ encBP, float* __restrict__ decBP,
                        float* __restrict__ fcT,
                        bf16* __restrict__ W0H, bf16* __restrict__ W0L,
                        bf16* __restrict__ WRH, bf16* __restrict__ WRL) {
    int job = blockIdx.y;
    int i = blockIdx.x * 256 + threadIdx.x;
    if (job == 0) {
        if (i < 2048) {
            int l = i >> 9, n = i & 511;
            encBP[i] = enc_b[l * 512 + ((n & 3) * 128 + (n >> 2))];
        } else if (i < 4096) {
            int i2 = i - 2048;
            int l = i2 >> 9, n = i2 & 511;
            decBP[i2] = dec_b[l * 512 + ((n & 3) * 128 + (n >> 2))];
        } else if (i < 4096 + H * IN_DIM) {
            int i2 = i - 4096;
            int k = i2 / IN_DIM, j = i2 - k * IN_DIM;
            fcT[i2] = fc_W[j * H + k];
        }
    } else if (job == 1) {
        if (i < 512 * 48) {
            int n = i / 48, k = i - n * 48;
            float w = 0.f;
            if (k < IN_DIM) w = Wih0[((n & 3) * 128 + (n >> 2)) * IN_DIM + k];
            split_bf16(w, W0H[i], W0L[i]);
        }
    } else {
        int r = job - 2;
        if (i < 512 * 128) {
            int n = i >> 7, k = i & 127;
            float w = WihR[(long)r * 512 * 128 + ((n & 3) * 128 + (n >> 2)) * 128 + k];
            split_bf16(w, WRH[(long)r * 512 * 128 + i], WRL[(long)r * 512 * 128 + i]);
        }
    }
}

// ---------------------------------------------------------------------------
// Prep kernel 3: gather x -> hi/lo bf16 [row][48] (row = t*BATCH + b)
// ---------------------------------------------------------------------------
__global__ void k_xconv(const float* __restrict__ x,
                        bf16* __restrict__ XH, bf16* __restrict__ XL) {
    for (long i = (long)blockIdx.x * 256 + threadIdx.x; i < (long)NROWS * 48;
         i += (long)gridDim.x * 256) {
        int row = (int)(i / 48), k = (int)(i - (long)row * 48);
        int t = row >> 11, b = row & 2047;
        float v = (k < IN_DIM) ? x[((long)b * SEQ + t) * IN_DIM + k] : 0.f;
        split_bf16(v, XH[i], XL[i]);
    }
}

// ---------------------------------------------------------------------------
// Persistent weight-resident split-bf16 tensor-core GEMM (ldmatrix, 512 thr).
//   out[r][n0+n] = biasP[n0+n] + sum_k A(r,k)*W[n0+n][k]
// grid (74, 2): 148 blocks, 1/SM, 16 warps. B resident; A streamed M=64.
// 16 warps = 2(M)x8(N); warp tile 32x32; 3 mma passes per k-step.
// ---------------------------------------------------------------------------
template <int K>
__global__ void __launch_bounds__(512, 1)
k_mmagemm(const bf16* __restrict__ AH, const bf16* __restrict__ AL,
          const bf16* __restrict__ WH, const bf16* __restrict__ WL,
          const float* __restrict__ biasP, float* __restrict__ out) {
    extern __shared__ char smc[];
    const int KSTEPS = K / 16;
    const int ROWB = (K + 8) * 2;          // padded row bytes
    const int BSP  = 256 * ROWB;           // one B split plane
    const int ASP  = 64 * ROWB;            // one A split plane
    const int CPR  = K / 8;                // 16B chunks per row

    char* Bb = smc;                        // [2 split][256][ROWB]
    char* Ab = smc + 2 * BSP;              // [2 buf][2 split][64][ROWB]
    float* bias_s = (float*)(smc + 2 * BSP + 4 * ASP);

    const int tid = threadIdx.x;
    const int n0 = blockIdx.y * 256;
    const int w = tid >> 5, lane = tid & 31;
    const int wm = w >> 3, wn = w & 7;     // 2 x 8 warp grid
    const int ar = lane >> 2, ac = (lane & 3) * 2;
    const int li = lane & 7, lq = lane >> 3;
    // ldmatrix per-lane byte offsets
    const int aoff = (li + (lq & 1) * 8) * ROWB + (lq >> 1) * 16;
    const int boff = (li + (lq >> 1) * 8) * ROWB + (lq & 1) * 16;

    const unsigned Bb_s = (unsigned)__cvta_generic_to_shared(Bb);
    const unsigned Ab_s = (unsigned)__cvta_generic_to_shared(Ab);

    if (tid < 256) bias_s[tid] = biasP[n0 + tid];

    // ---- stage B (resident, once) ----
    {
        const int total = 2 * 256 * CPR;
        for (int i = tid; i < total; i += 512) {
            int split = i / (256 * CPR);
            int rem = i - split * 256 * CPR;
            int n = rem / CPR, ch = rem - n * CPR;
            const bf16* src = (split ? WL : WH) + (long)(n0 + n) * K + ch * 8;
            unsigned dst = (unsigned)__cvta_generic_to_shared(
                Bb + split * BSP + n * ROWB + ch * 16);
            cp16(dst, src);
        }
        cp_commit();
    }

    // ---- A stage lambda ----
    auto issueA = [&](int mt, int buf) {
        const int total = 2 * 64 * CPR;
        for (int i = tid; i < total; i += 512) {
            int split = i / (64 * CPR);
            int rem = i - split * 64 * CPR;
            int row = rem / CPR, ch = rem - row * CPR;
            const bf16* src = (split ? AL : AH) + (long)(mt * 64 + row) * K + ch * 8;
            unsigned dst = (unsigned)__cvta_generic_to_shared(
                Ab + buf * 2 * ASP + split * ASP + row * ROWB + ch * 16);
            cp16(dst, src);
        }
        cp_commit();
    };

    issueA(blockIdx.x, 0);
    cp_wait0();
    __syncthreads();

    int it = 0;
    for (int mt = blockIdx.x; mt < MT64; mt += GBX, ++it) {
        const int buf = it & 1;
        const bool more = (mt + GBX < MT64);
        if (more) issueA(mt + GBX, buf ^ 1);

        const unsigned Ahb = Ab_s + buf * 2 * ASP;

        float acc[2][4][4];
#pragma unroll
        for (int mi = 0; mi < 2; ++mi)
#pragma unroll
            for (int ni = 0; ni < 4; ++ni)
#pragma unroll
                for (int q = 0; q < 4; ++q) acc[mi][ni][q] = 0.f;

#pragma unroll
        for (int ks = 0; ks < KSTEPS; ++ks) {
            const int kb2 = ks * 32;
            uint32_t ah[2][4], al[2][4];
#pragma unroll
            for (int mi = 0; mi < 2; ++mi) {
                unsigned base = Ahb + (wm * 32 + mi * 16) * ROWB + kb2 + aoff;
                LDSM4(ah[mi], base);
                LDSM4(al[mi], base + ASP);
            }
            uint32_t bhf[2][4], blf[2][4];   // [pair p][4 regs = 2 n8 tiles]
#pragma unroll
            for (int p = 0; p < 2; ++p) {
                unsigned nb = Bb_s + (wn * 32 + p * 16) * ROWB + kb2 + boff;
                LDSM4(bhf[p], nb);
                LDSM4(blf[p], nb + BSP);
            }
#pragma unroll
            for (int p = 0; p < 2; ++p) {
#pragma unroll
                for (int hh = 0; hh < 2; ++hh) {
                    int ni = p * 2 + hh;
                    uint32_t* bH = &bhf[p][hh * 2];
                    uint32_t* bL = &blf[p][hh * 2];
                    MMA_BF16(acc[0][ni], ah[0], bH);
                    MMA_BF16(acc[1][ni], ah[1], bH);
                    MMA_BF16(acc[0][ni], ah[0], bL);
                    MMA_BF16(acc[1][ni], ah[1], bL);
                    MMA_BF16(acc[0][ni], al[0], bH);
                    MMA_BF16(acc[1][ni], al[1], bH);
                }
            }
        }

        // ---- epilogue: bias + store ----
        const int m0 = mt * 64;
#pragma unroll
        for (int mi = 0; mi < 2; ++mi) {
            int r = m0 + wm * 32 + mi * 16 + ar;
#pragma unroll
            for (int ni = 0; ni < 4; ++ni) {
                int cl = wn * 32 + ni * 8 + ac;
                float b0 = bias_s[cl], b1 = bias_s[cl + 1];
                float2 v0 = { acc[mi][ni][0] + b0, acc[mi][ni][1] + b1 };
                float2 v1 = { acc[mi][ni][2] + b0, acc[mi][ni][3] + b1 };
                *(float2*)&out[(long)r * H4 + n0 + cl] = v0;
                *(float2*)&out[(long)(r + 8) * H4 + n0 + cl] = v1;
            }
        }
        if (more) { cp_wait0(); __syncthreads(); }
    }
}

// ---------------------------------------------------------------------------
// Encoder recurrent sweep; 147 blocks, 14 used rows (stride 16).
// ---------------------------------------------------------------------------
template <bool WRITE_YS>
__global__ void __launch_bounds__(256, 1) k_lstm_seq(const float4* __restrict__ Wp,
                                                     bf16* __restrict__ ysH,
                                                     bf16* __restrict__ ysL,
                                                     float* __restrict__ hfin,
                                                     float* __restrict__ cfin) {
    __shared__ float h_s[2][H][TBS];
    const int tid = threadIdx.x;
    const int c = tid & 127, bh = tid >> 7;
    const int b0 = blockIdx.x * TBU;

    int bcl[8];     // clamped global batch rows for loads
    bool wr[8];     // write guards
#pragma unroll
    for (int b = 0; b < 8; ++b) {
        int lb = bh * 8 + b;
        int gb = b0 + lb;
        bcl[b] = gb < BATCH ? gb : BATCH - 1;
        wr[b] = (lb < TBU) && (gb < BATCH);
    }

    for (int i = tid; i < H * TBS; i += 256) (&h_s[1][0][0])[i] = 0.f;
    float c_reg[8] = {0.f, 0.f, 0.f, 0.f, 0.f, 0.f, 0.f, 0.f};
    __syncthreads();

    const float4* wp = Wp + c;
    for (int t = 0; t < SEQ; ++t) {
        const float4* xgt = (const float4*)(g_Xg + (long)t * BATCH * H4) + c;
        float4 xr[8];
#pragma unroll
        for (int b = 0; b < 8; ++b) xr[b] = xgt[(long)bcl[b] * 128];

        ull acc[4][4];
        ull z = pack2(0.f, 0.f);
#pragma unroll
        for (int g = 0; g < 4; ++g)
#pragma unroll
            for (int p = 0; p < 4; ++p) acc[g][p] = z;

        const float* hp = &h_s[(t + 1) & 1][0][bh * 8];
#pragma unroll 8
        for (int k = 0; k < H; ++k) {
            float4 w = wp[k * 128];
            ulonglong2 hA = *(const ulonglong2*)(hp + k * TBS);
            ulonglong2 hB = *(const ulonglong2*)(hp + k * TBS + 4);
            ull w0 = pack2(w.x, w.x);
            ffma2(acc[0][0], w0, hA.x); ffma2(acc[0][1], w0, hA.y);
            ffma2(acc[0][2], w0, hB.x); ffma2(acc[0][3], w0, hB.y);
            ull w1 = pack2(w.y, w.y);
            ffma2(acc[1][0], w1, hA.x); ffma2(acc[1][1], w1, hA.y);
            ffma2(acc[1][2], w1, hB.x); ffma2(acc[1][3], w1, hB.y);
            ull w2 = pack2(w.z, w.z);
            ffma2(acc[2][0], w2, hA.x); ffma2(acc[2][1], w2, hA.y);
            ffma2(acc[2][2], w2, hB.x); ffma2(acc[2][3], w2, hB.y);
            ull w3 = pack2(w.w, w.w);
            ffma2(acc[3][0], w3, hA.x); ffma2(acc[3][1], w3, hA.y);
            ffma2(acc[3][2], w3, hB.x); ffma2(acc[3][3], w3, hB.y);
        }
        float hv[8];
#pragma unroll
        for (int p = 0; p < 4; ++p) {
            float i0, i1, f0, f1, g0, g1, o0, o1;
            unpack2(acc[0][p], i0, i1);
            unpack2(acc[1][p], f0, f1);
            unpack2(acc[2][p], g0, g1);
            unpack2(acc[3][p], o0, o1);
            int b = 2 * p;
            {
                float gi = i0 + xr[b].x, gf = f0 + xr[b].y;
                float gg = g0 + xr[b].z, go = o0 + xr[b].w;
                float cn = sigf(gf) * c_reg[b] + sigf(gi) * tanha(gg);
                c_reg[b] = cn;
                hv[b] = sigf(go) * tanha(cn);
            }
            b = 2 * p + 1;
            {
                float gi = i1 + xr[b].x, gf = f1 + xr[b].y;
                float gg = g1 + xr[b].z, go = o1 + xr[b].w;
                float cn = sigf(gf) * c_reg[b] + sigf(gi) * tanha(gg);
                c_reg[b] = cn;
                hv[b] = sigf(go) * tanha(cn);
            }
        }
        float* hw = &h_s[t & 1][c][bh * 8];
        *(float4*)hw       = make_float4(hv[0], hv[1], hv[2], hv[3]);
        *(float4*)(hw + 4) = make_float4(hv[4], hv[5], hv[6], hv[7]);
        if (WRITE_YS) {
            long base_t = (long)t * BATCH * H;
#pragma unroll
            for (int b = 0; b < 8; ++b) {
                if (wr[b]) {
                    bf16 hh, hl;
                    split_bf16(hv[b], hh, hl);
                    long idx = base_t + (long)(b0 + bh * 8 + b) * H + c;
                    ysH[idx] = hh;
                    ysL[idx] = hl;
                }
            }
        }
        __syncthreads();
    }
#pragma unroll
    for (int b = 0; b < 8; ++b) {
        if (wr[b]) {
            hfin[(b0 + bh * 8 + b) * H + c] = h_s[1][c][bh * 8 + b];
            cfin[(b0 + bh * 8 + b) * H + c] = c_reg[b];
        }
    }
}

// ---------------------------------------------------------------------------
// Fused decoder: 147 blocks, 14 used rows (stride 16).
// ---------------------------------------------------------------------------
#define DSM_H   (NL * 2 * H * TBS)     // 16384 floats
#define DSM_FCW (H * IN_DIM)           // 5632
#define DSM_DIN (IN_DIM * TBS)         // 704
#define DSM_FCB 48
#define DEC_SMEM_BYTES ((DSM_H + DSM_FCW + DSM_DIN + DSM_FCB) * 4)

__global__ void __launch_bounds__(256, 1) k_decoder(const float* __restrict__ x,
                                                    const float* __restrict__ fc_b,
                                                    float* __restrict__ out) {
    extern __shared__ float sm[];
    float* h_s = sm;
    float* fcw = sm + DSM_H;
    float* din = fcw + DSM_FCW;
    float* fcb = din + DSM_DIN;

    const int tid = threadIdx.x;
    const int c = tid & 127, bh = tid >> 7;
    const int b0 = blockIdx.x * TBU;

    for (int i = tid; i < NL * H * TBS; i += 256) {
        int l = i / (H * TBS);
        int r = i - l * (H * TBS);
        int k = r / TBS, b = r - k * TBS;
        int gb = b0 + b; if (gb >= BATCH) gb = BATCH - 1;
        h_s[((l * 2 + 1) * H + k) * TBS + b] = g_h[((long)l * BATCH + gb) * H + k];
    }
    float c_reg[NL * 8];
#pragma unroll
    for (int l = 0; l < NL; ++l)
#pragma unroll
        for (int b = 0; b < 8; ++b) {
            int gb = b0 + bh * 8 + b; if (gb >= BATCH) gb = BATCH - 1;
            c_reg[l * 8 + b] = g_c[((long)l * BATCH + gb) * H + c];
        }
    for (int i = tid; i < DSM_FCW; i += 256) fcw[i] = g_fcT[i];
    for (int i = tid; i < IN_DIM * TBS; i += 256) {
        int k = i >> 4, b = i & 15;
        int gb = b0 + b; if (gb >= BATCH) gb = BATCH - 1;
        din[i] = x[((long)gb * SEQ + (SEQ - 1)) * IN_DIM + k];
    }
    for (int i = tid; i < IN_DIM; i += 256) fcb[i] = fc_b[i];
    __syncthreads();

    float4 bias[NL];
#pragma unroll
    for (int l = 0; l < NL; ++l)
        bias[l] = *(const float4*)&g_decBP[l * H4 + 4 * c];

    for (int t = 0; t < TDEC; ++t) {
        const int cur = t & 1, prv = cur ^ 1;
#pragma unroll 1
        for (int l = 0; l < NL; ++l) {
            ull acc[4][4];
            ull z = pack2(0.f, 0.f);
#pragma unroll
            for (int g = 0; g < 4; ++g)
#pragma unroll
                for (int p = 0; p < 4; ++p) acc[g][p] = z;

            {
                const float4* wr = (const float4*)g_decWhhP4 + (long)l * H * H + c;
                const float* hp = &h_s[(l * 2 + prv) * H * TBS + bh * 8];
#pragma unroll 8
                for (int k = 0; k < H; ++k) {
                    float4 w = wr[k * 128];
                    ulonglong2 hA = *(const ulonglong2*)(hp + k * TBS);
                    ulonglong2 hB = *(const ulonglong2*)(hp + k * TBS + 4);
                    ull w0 = pack2(w.x, w.x);
                    ffma2(acc[0][0], w0, hA.x); ffma2(acc[0][1], w0, hA.y);
                    ffma2(acc[0][2], w0, hB.x); ffma2(acc[0][3], w0, hB.y);
                    ull w1 = pack2(w.y, w.y);
                    ffma2(acc[1][0], w1, hA.x); ffma2(acc[1][1], w1, hA.y);
                    ffma2(acc[1][2], w1, hB.x); ffma2(acc[1][3], w1, hB.y);
                    ull w2 = pack2(w.z, w.z);
                    ffma2(acc[2][0], w2, hA.x); ffma2(acc[2][1], w2, hA.y);
                    ffma2(acc[2][2], w2, hB.x); ffma2(acc[2][3], w2, hB.y);
                    ull w3 = pack2(w.w, w.w);
                    ffma2(acc[3][0], w3, hA.x); ffma2(acc[3][1], w3, hA.y);
                    ffma2(acc[3][2], w3, hB.x); ffma2(acc[3][3], w3, hB.y);
                }
            }
            if (l == 0) {
                const float4* wi = (const float4*)g_decWih0P4 + c;
                const float* dp = din + bh * 8;
#pragma unroll 4
                for (int k = 0; k < IN_DIM; ++k) {
                    float4 w = wi[k * 128];
                    ulonglong2 dA = *(const ulonglong2*)(dp + k * TBS);
                    ulonglong2 dB = *(const ulonglong2*)(dp + k * TBS + 4);
                    ull w0 = pack2(w.x, w.x);
                    ffma2(acc[0][0], w0, dA.x); ffma2(acc[0][1], w0, dA.y);
                    ffma2(acc[0][2], w0, dB.x); ffma2(acc[0][3], w0, dB.y);
                    ull w1 = pack2(w.y, w.y);
                    ffma2(acc[1][0], w1, dA.x); ffma2(acc[1][1], w1, dA.y);
                    ffma2(acc[1][2], w1, dB.x); ffma2(acc[1][3], w1, dB.y);
                    ull w2 = pack2(w.z, w.z);
                    ffma2(acc[2][0], w2, dA.x); ffma2(acc[2][1], w2, dA.y);
                    ffma2(acc[2][2], w2, dB.x); ffma2(acc[2][3], w2, dB.y);
                    ull w3 = pack2(w.w, w.w);
                    ffma2(acc[3][0], w3, dA.x); ffma2(acc[3][1], w3, dA.y);
                    ffma2(acc[3][2], w3, dB.x); ffma2(acc[3][3], w3, dB.y);
                }
            } else {
                const float4* wi = (const float4*)g_decWihRP4 + (long)(l - 1) * H * H + c;
                const float* hp2 = &h_s[((l - 1) * 2 + cur) * H * TBS + bh * 8];
#pragma unroll 8
                for (int k = 0; k < H; ++k) {
                    float4 w = wi[k * 128];
                    ulonglong2 hA = *(const ulonglong2*)(hp2 + k * TBS);
                    ulonglong2 hB = *(const ulonglong2*)(hp2 + k * TBS + 4);
                    ull w0 = pack2(w.x, w.x);
                    ffma2(acc[0][0], w0, hA.x); ffma2(acc[0][1], w0, hA.y);
                    ffma2(acc[0][2], w0, hB.x); ffma2(acc[0][3], w0, hB.y);
                    ull w1 = pack2(w.y, w.y);
                    ffma2(acc[1][0], w1, hA.x); ffma2(acc[1][1], w1, hA.y);
                    ffma2(acc[1][2], w1, hB.x); ffma2(acc[1][3], w1, hB.y);
                    ull w2 = pack2(w.z, w.z);
                    ffma2(acc[2][0], w2, hA.x); ffma2(acc[2][1], w2, hA.y);
                    ffma2(acc[2][2], w2, hB.x); ffma2(acc[2][3], w2, hB.y);
                    ull w3 = pack2(w.w, w.w);
                    ffma2(acc[3][0], w3, hA.x); ffma2(acc[3][1], w3, hA.y);
                    ffma2(acc[3][2], w3, hB.x); ffma2(acc[3][3], w3, hB.y);
                }
            }
            float4 bb = bias[l];
            float hv[8];
#pragma unroll
            for (int p = 0; p < 4; ++p) {
                float i0, i1, f0, f1, g0, g1, o0, o1;
                unpack2(acc[0][p], i0, i1);
                unpack2(acc[1][p], f0, f1);
                unpack2(acc[2][p], g0, g1);
                unpack2(acc[3][p], o0, o1);
                int b = 2 * p;
                {
                    float gi = i0 + bb.x, gf = f0 + bb.y, gg = g0 + bb.z, go = o0 + bb.w;
                    float cn = sigf(gf) * c_reg[l * 8 + b] + sigf(gi) * tanha(gg);
                    c_reg[l * 8 + b] = cn;
                    hv[b] = sigf(go) * tanha(cn);
                }
                b = 2 * p + 1;
                {
                    float gi = i1 + bb.x, gf = f1 + bb.y, gg = g1 + bb.z, go = o1 + bb.w;
                    float cn = sigf(gf) * c_reg[l * 8 + b] + sigf(gi) * tanha(gg);
                    c_reg[l * 8 + b] = cn;
                    hv[b] = sigf(go) * tanha(cn);
                }
            }
            float* hw = &h_s[((l * 2 + cur) * H + c) * TBS + bh * 8];
            *(float4*)hw       = make_float4(hv[0], hv[1], hv[2], hv[3]);
            *(float4*)(hw + 4) = make_float4(hv[4], hv[5], hv[6], hv[7]);
            __syncthreads();
        }
        const float* h3 = &h_s[(3 * 2 + cur) * H * TBS];
        for (int idx = tid; idx < TBS * IN_DIM; idx += 256) {
            int b = idx / IN_DIM, j = idx - b * IN_DIM;
            float s = fcb[j];
#pragma unroll 8
            for (int k = 0; k < H; ++k)
                s += h3[k * TBS + b] * fcw[k * IN_DIM + j];
            if (b < TBU && b0 + b < BATCH)
                out[((long)(b0 + b) * TDEC + t) * IN_DIM + j] = s;
            din[j * TBS + b] = s;
        }
        __syncthreads();
    }
}

// ---------------------------------------------------------------------------
// Host launcher
// ---------------------------------------------------------------------------
extern "C" void kernel_launch(void* const* d_in, const int* in_sizes, int n_in,
                              void* d_out, int out_size) {
    const float* x        = (const float*)d_in[0];
    const float* enc_Wih0 = (const float*)d_in[2];
    const float* enc_WihR = (const float*)d_in[3];
    const float* enc_Whh  = (const float*)d_in[4];
    const float* enc_b    = (const float*)d_in[5];
    const float* dec_Wih0 = (const float*)d_in[6];
    const float* dec_WihR = (const float*)d_in[7];
    const float* dec_Whh  = (const float*)d_in[8];
    const float* dec_b    = (const float*)d_in[9];
    const float* fc_W     = (const float*)d_in[10];
    const float* fc_b     = (const float*)d_in[11];
    float* out = (float*)d_out;

    float *encBP, *decBP;
    float *encWhhP4, *decWhhP4, *decWihRP4, *decWih0P4, *fcT;
    float *Xg, *hSt, *cSt;
    bf16 *W0H, *W0L, *WRH, *WRL, *ysH, *ysL, *x0H, *x0L;
    cudaGetSymbolAddress((void**)&encBP,     g_encBP);
    cudaGetSymbolAddress((void**)&decBP,     g_decBP);
    cudaGetSymbolAddress((void**)&encWhhP4,  g_encWhhP4);
    cudaGetSymbolAddress((void**)&decWhhP4,  g_decWhhP4);
    cudaGetSymbolAddress((void**)&decWihRP4, g_decWihRP4);
    cudaGetSymbolAddress((void**)&decWih0P4, g_decWih0P4);
    cudaGetSymbolAddress((void**)&fcT,       g_fcT);
    cudaGetSymbolAddress((void**)&Xg,        g_Xg);
    cudaGetSymbolAddress((void**)&hSt,       g_h);
    cudaGetSymbolAddress((void**)&cSt,       g_c);
    cudaGetSymbolAddress((void**)&W0H,       g_W0H);
    cudaGetSymbolAddress((void**)&W0L,       g_W0L);
    cudaGetSymbolAddress((void**)&WRH,       g_WRH);
    cudaGetSymbolAddress((void**)&WRL,       g_WRL);
    cudaGetSymbolAddress((void**)&ysH,       g_ysH);
    cudaGetSymbolAddress((void**)&ysL,       g_ysL);
    cudaGetSymbolAddress((void**)&x0H,       g_x0H);
    cudaGetSymbolAddress((void**)&x0L,       g_x0L);

    cudaFuncSetAttribute(k_decoder, cudaFuncAttributeMaxDynamicSharedMemorySize,
                         DEC_SMEM_BYTES);
    const int DYN48  = 2 * (256 * 112) + 4 * (64 * 112) + 1024;   // 87,040
    const int DYN128 = 2 * (256 * 272) + 4 * (64 * 272) + 1024;   // 210,944
    cudaFuncSetAttribute(k_mmagemm<48>,
                         cudaFuncAttributeMaxDynamicSharedMemorySize, DYN48);
    cudaFuncSetAttribute(k_mmagemm<128>,
                         cudaFuncAttributeMaxDynamicSharedMemorySize, DYN128);

    // prep (3 launches)
    {
        GPJobs jg; jg.n = 12;
        for (int l = 0; l < NL; ++l)
            jg.j[l] = { enc_Whh + (long)l * H4 * H, encWhhP4 + (long)l * H * H * 4, H };
        for (int l = 0; l < NL; ++l)
            jg.j[4 + l] = { dec_Whh + (long)l * H4 * H, decWhhP4 + (long)l * H * H * 4, H };
        for (int r = 0; r < 3; ++r)
            jg.j[8 + r] = { dec_WihR + (long)r * H4 * H, decWihRP4 + (long)r * H * H * 4, H };
        jg.j[11] = { dec_Wih0, decWih0P4, IN_DIM };
        dim3 g(128, 12);
        k_pack4g<<<g, 128>>>(jg);
    }
    {
        dim3 g(256, 5);
        k_wconv<<<g, 256>>>(enc_b, dec_b, fc_W, enc_Wih0, enc_WihR,
                            encBP, decBP, fcT, W0H, W0L, WRH, WRL);
    }
    k_xconv<<<2048, 256>>>(x, x0H, x0L);

    dim3 ggrid(GBX, 2);

    // encoder layer 0
    k_mmagemm<48><<<ggrid, 512, DYN48>>>(x0H, x0L, W0H, W0L, encBP, Xg);
    k_lstm_seq<true><<<RBLK, 256>>>((const float4*)encWhhP4, ysH, ysL, hSt, cSt);
    // encoder layers 1..3
    for (int l = 1; l < NL; ++l) {
        k_mmagemm<128><<<ggrid, 512, DYN128>>>(
            ysH, ysL, WRH + (long)(l - 1) * 512 * 128, WRL + (long)(l - 1) * 512 * 128,
            encBP + (long)l * H4, Xg);
        if (l < NL - 1)
            k_lstm_seq<true><<<RBLK, 256>>>(
                (const float4*)(encWhhP4 + (long)l * H * H * 4), ysH, ysL,
                hSt + (long)l * BATCH * H, cSt + (long)l * BATCH * H);
        else
            k_lstm_seq<false><<<RBLK, 256>>>(
                (const float4*)(encWhhP4 + (long)l * H * H * 4), nullptr, nullptr,
                hSt + (long)l * BATCH * H, cSt + (long)l * BATCH * H);
    }
    // fused decoder
    k_decoder<<<RBLK, 256, DEC_SMEM_BYTES>>>(x, fc_b, out);
}

// round 12
// speedup vs baseline: 1.0932x; 1.0932x over previous
#include <cuda_runtime.h>
#include <cuda_bf16.h>
#include <cstdint>
#include <math.h>

// Problem constants
#define IN_DIM 44
#define H      128
#define H4     512
#define NL     4
#define TDEC   50
#define BATCH  2048
#define SEQ    200

#define TBS 16                       // batch tile stride (smem layout)
#define TBU 14                       // batch rows actually used per block
#define RBLK ((BATCH + TBU - 1) / TBU)   // 147 recurrent/decoder blocks
#define NROWS (SEQ * BATCH)          // 409600 GEMM rows
#define MT64  (NROWS / 64)           // 6400 m-tiles
#define GBX   74                     // GEMM persistent blocks per N-half
#define WC    96                     // recurrent weight k-rows cached in smem

typedef unsigned long long ull;
typedef __nv_bfloat16 bf16;

// ---------------------------------------------------------------------------
// Device scratch
// ---------------------------------------------------------------------------
__device__ float g_Xg[(long)NROWS * H4];        // gate-interleaved: [row][4c+g]
__device__ bf16  g_ysH[(long)NROWS * H];        // layer output hi plane [row][k]
__device__ bf16  g_ysL[(long)NROWS * H];        // layer output lo plane
__device__ bf16  g_x0H[(long)NROWS * 48];       // gathered x hi plane [row][48]
__device__ bf16  g_x0L[(long)NROWS * 48];
__device__ float g_h[NL * BATCH * H];
__device__ float g_c[NL * BATCH * H];
// permuted biases [l][4c+g]
__device__ float g_encBP[NL * H4];
__device__ float g_decBP[NL * H4];
// gate-grouped packed recurrent/input weights: float4[k*128+c] = {Wi,Wf,Wg,Wo}[c][k]
__device__ float g_encWhhP4[NL * H * H * 4];
__device__ float g_decWhhP4[NL * H * H * 4];
__device__ float g_decWihRP4[3 * H * H * 4];
__device__ float g_decWih0P4[IN_DIM * H * 4];
__device__ float g_fcT[H * IN_DIM];
// bf16 hi/lo GEMM weight planes, gate-permuted [n][k] (k padded)
__device__ bf16 g_W0H[512 * 48];
__device__ bf16 g_W0L[512 * 48];
__device__ bf16 g_WRH[3 * 512 * 128];
__device__ bf16 g_WRL[3 * 512 * 128];

// ---------------------------------------------------------------------------
// packed f32x2 helpers
// ---------------------------------------------------------------------------
__device__ __forceinline__ ull pack2(float a, float b) {
    ull r; asm("mov.b64 %0, {%1,%2};" : "=l"(r) : "f"(a), "f"(b)); return r;
}
__device__ __forceinline__ void unpack2(ull v, float& a, float& b) {
    asm("mov.b64 {%0,%1}, %2;" : "=f"(a), "=f"(b) : "l"(v));
}
__device__ __forceinline__ void ffma2(ull& d, ull a, ull b) {
    asm("fma.rn.f32x2 %0, %1, %2, %0;" : "+l"(d) : "l"(a), "l"(b));
}

// activations via MUFU.TANH
__device__ __forceinline__ float tanha(float x) {
    float y; asm("tanh.approx.f32 %0, %1;" : "=f"(y) : "f"(x)); return y;
}
__device__ __forceinline__ float sigf(float x) {
    return 0.5f * tanha(0.5f * x) + 0.5f;
}

// cp.async helpers
__device__ __forceinline__ void cp16(unsigned int dst, const void* src) {
    asm volatile("cp.async.ca.shared.global [%0], [%1], 16;"
                 :: "r"(dst), "l"(src));
}
__device__ __forceinline__ void cp_commit() {
    asm volatile("cp.async.commit_group;");
}
__device__ __forceinline__ void cp_wait0() {
    asm volatile("cp.async.wait_group 0;");
}

// bf16 mma m16n8k16, f32 accum (HMMA path — works on plain sm_103)
#define MMA_BF16(d, a, b)                                                     \
    asm volatile(                                                             \
        "mma.sync.aligned.m16n8k16.row.col.f32.bf16.bf16.f32 "                \
        "{%0,%1,%2,%3}, {%4,%5,%6,%7}, {%8,%9}, {%0,%1,%2,%3};"               \
        : "+f"((d)[0]), "+f"((d)[1]), "+f"((d)[2]), "+f"((d)[3])              \
        : "r"((a)[0]), "r"((a)[1]), "r"((a)[2]), "r"((a)[3]),                 \
          "r"((b)[0]), "r"((b)[1]))

#define LDSM4(r, addr)                                                        \
    asm volatile("ldmatrix.sync.aligned.m8n8.x4.shared.b16 "                  \
        "{%0,%1,%2,%3}, [%4];"                                                \
        : "=r"((r)[0]), "=r"((r)[1]), "=r"((r)[2]), "=r"((r)[3])              \
        : "r"(addr))

__device__ __forceinline__ void split_bf16(float v, bf16& h, bf16& l) {
    h = __float2bfloat16_rn(v);
    l = __float2bfloat16_rn(v - __bfloat162float(h));
}

// ---------------------------------------------------------------------------
// Prep kernel 1: gate-grouped 4-pack for recurrent kernels
// ---------------------------------------------------------------------------
struct GPJob { const float* s; float* d; int K; };
struct GPJobs { GPJob j[12]; int n; };

__global__ void k_pack4g(GPJobs jobs) {
    int job = blockIdx.y;
    if (job >= jobs.n) return;
    GPJob J = jobs.j[job];
    int i = blockIdx.x * 128 + threadIdx.x;
    if (i < J.K * 128) {
        int k = i >> 7, c = i & 127;
        float4 v;
        v.x = J.s[c * J.K + k];
        v.y = J.s[(128 + c) * J.K + k];
        v.z = J.s[(256 + c) * J.K + k];
        v.w = J.s[(384 + c) * J.K + k];
        ((float4*)J.d)[i] = v;
    }
}

// ---------------------------------------------------------------------------
// Prep kernel 2 (merged): biases/fcT + GEMM weight hi/lo planes
// ---------------------------------------------------------------------------
__global__ void k_wconv(const float* __restrict__ enc_b, const float* __restrict__ dec_b,
                        const float* __restrict__ fc_W,
                        const float* __restrict__ Wih0, const float* __restrict__ WihR,
                        float* __restrict__ encBP, float* __restrict__ decBP,
                        float* __restrict__ fcT,
                        bf16* __restrict__ W0H, bf16* __restrict__ W0L,
                        bf16* __restrict__ WRH, bf16* __restrict__ WRL) {
    int job = blockIdx.y;
    int i = blockIdx.x * 256 + threadIdx.x;
    if (job == 0) {
        if (i < 2048) {
            int l = i >> 9, n = i & 511;
            encBP[i] = enc_b[l * 512 + ((n & 3) * 128 + (n >> 2))];
        } else if (i < 4096) {
            int i2 = i - 2048;
            int l = i2 >> 9, n = i2 & 511;
            decBP[i2] = dec_b[l * 512 + ((n & 3) * 128 + (n >> 2))];
        } else if (i < 4096 + H * IN_DIM) {
            int i2 = i - 4096;
            int k = i2 / IN_DIM, j = i2 - k * IN_DIM;
            fcT[i2] = fc_W[j * H + k];
        }
    } else if (job == 1) {
        if (i < 512 * 48) {
            int n = i / 48, k = i - n * 48;
            float w = 0.f;
            if (k < IN_DIM) w = Wih0[((n & 3) * 128 + (n >> 2)) * IN_DIM + k];
            split_bf16(w, W0H[i], W0L[i]);
        }
    } else {
        int r = job - 2;
        if (i < 512 * 128) {
            int n = i >> 7, k = i & 127;
            float w = WihR[(long)r * 512 * 128 + ((n & 3) * 128 + (n >> 2)) * 128 + k];
            split_bf16(w, WRH[(long)r * 512 * 128 + i], WRL[(long)r * 512 * 128 + i]);
        }
    }
}

// ---------------------------------------------------------------------------
// Prep kernel 3: gather x -> hi/lo bf16 [row][48] (row = t*BATCH + b)
// ---------------------------------------------------------------------------
__global__ void k_xconv(const float* __restrict__ x,
                        bf16* __restrict__ XH, bf16* __restrict__ XL) {
    for (long i = (long)blockIdx.x * 256 + threadIdx.x; i < (long)NROWS * 48;
         i += (long)gridDim.x * 256) {
        int row = (int)(i / 48), k = (int)(i - (long)row * 48);
        int t = row >> 11, b = row & 2047;
        float v = (k < IN_DIM) ? x[((long)b * SEQ + t) * IN_DIM + k] : 0.f;
        split_bf16(v, XH[i], XL[i]);
    }
}

// ---------------------------------------------------------------------------
// Persistent weight-resident split-bf16 tensor-core GEMM (ldmatrix, 512 thr).
// ---------------------------------------------------------------------------
template <int K>
__global__ void __launch_bounds__(512, 1)
k_mmagemm(const bf16* __restrict__ AH, const bf16* __restrict__ AL,
          const bf16* __restrict__ WH, const bf16* __restrict__ WL,
          const float* __restrict__ biasP, float* __restrict__ out) {
    extern __shared__ char smc[];
    const int KSTEPS = K / 16;
    const int ROWB = (K + 8) * 2;          // padded row bytes
    const int BSP  = 256 * ROWB;           // one B split plane
    const int ASP  = 64 * ROWB;            // one A split plane
    const int CPR  = K / 8;                // 16B chunks per row

    char* Bb = smc;                        // [2 split][256][ROWB]
    char* Ab = smc + 2 * BSP;              // [2 buf][2 split][64][ROWB]
    float* bias_s = (float*)(smc + 2 * BSP + 4 * ASP);

    const int tid = threadIdx.x;
    const int n0 = blockIdx.y * 256;
    const int w = tid >> 5, lane = tid & 31;
    const int wm = w >> 3, wn = w & 7;     // 2 x 8 warp grid
    const int ar = lane >> 2, ac = (lane & 3) * 2;
    const int li = lane & 7, lq = lane >> 3;
    const int aoff = (li + (lq & 1) * 8) * ROWB + (lq >> 1) * 16;
    const int boff = (li + (lq >> 1) * 8) * ROWB + (lq & 1) * 16;

    const unsigned Bb_s = (unsigned)__cvta_generic_to_shared(Bb);
    const unsigned Ab_s = (unsigned)__cvta_generic_to_shared(Ab);

    if (tid < 256) bias_s[tid] = biasP[n0 + tid];

    // ---- stage B (resident, once) ----
    {
        const int total = 2 * 256 * CPR;
        for (int i = tid; i < total; i += 512) {
            int split = i / (256 * CPR);
            int rem = i - split * 256 * CPR;
            int n = rem / CPR, ch = rem - n * CPR;
            const bf16* src = (split ? WL : WH) + (long)(n0 + n) * K + ch * 8;
            unsigned dst = (unsigned)__cvta_generic_to_shared(
                Bb + split * BSP + n * ROWB + ch * 16);
            cp16(dst, src);
        }
        cp_commit();
    }

    auto issueA = [&](int mt, int buf) {
        const int total = 2 * 64 * CPR;
        for (int i = tid; i < total; i += 512) {
            int split = i / (64 * CPR);
            int rem = i - split * 64 * CPR;
            int row = rem / CPR, ch = rem - row * CPR;
            const bf16* src = (split ? AL : AH) + (long)(mt * 64 + row) * K + ch * 8;
            unsigned dst = (unsigned)__cvta_generic_to_shared(
                Ab + buf * 2 * ASP + split * ASP + row * ROWB + ch * 16);
            cp16(dst, src);
        }
        cp_commit();
    };

    issueA(blockIdx.x, 0);
    cp_wait0();
    __syncthreads();

    int it = 0;
    for (int mt = blockIdx.x; mt < MT64; mt += GBX, ++it) {
        const int buf = it & 1;
        const bool more = (mt + GBX < MT64);
        if (more) issueA(mt + GBX, buf ^ 1);

        const unsigned Ahb = Ab_s + buf * 2 * ASP;

        float acc[2][4][4];
#pragma unroll
        for (int mi = 0; mi < 2; ++mi)
#pragma unroll
            for (int ni = 0; ni < 4; ++ni)
#pragma unroll
                for (int q = 0; q < 4; ++q) acc[mi][ni][q] = 0.f;

#pragma unroll
        for (int ks = 0; ks < KSTEPS; ++ks) {
            const int kb2 = ks * 32;
            uint32_t ah[2][4], al[2][4];
#pragma unroll
            for (int mi = 0; mi < 2; ++mi) {
                unsigned base = Ahb + (wm * 32 + mi * 16) * ROWB + kb2 + aoff;
                LDSM4(ah[mi], base);
                LDSM4(al[mi], base + ASP);
            }
            uint32_t bhf[2][4], blf[2][4];
#pragma unroll
            for (int p = 0; p < 2; ++p) {
                unsigned nb = Bb_s + (wn * 32 + p * 16) * ROWB + kb2 + boff;
                LDSM4(bhf[p], nb);
                LDSM4(blf[p], nb + BSP);
            }
#pragma unroll
            for (int p = 0; p < 2; ++p) {
#pragma unroll
                for (int hh = 0; hh < 2; ++hh) {
                    int ni = p * 2 + hh;
                    uint32_t* bH = &bhf[p][hh * 2];
                    uint32_t* bL = &blf[p][hh * 2];
                    MMA_BF16(acc[0][ni], ah[0], bH);
                    MMA_BF16(acc[1][ni], ah[1], bH);
                    MMA_BF16(acc[0][ni], ah[0], bL);
                    MMA_BF16(acc[1][ni], ah[1], bL);
                    MMA_BF16(acc[0][ni], al[0], bH);
                    MMA_BF16(acc[1][ni], al[1], bH);
                }
            }
        }

        const int m0 = mt * 64;
#pragma unroll
        for (int mi = 0; mi < 2; ++mi) {
            int r = m0 + wm * 32 + mi * 16 + ar;
#pragma unroll
            for (int ni = 0; ni < 4; ++ni) {
                int cl = wn * 32 + ni * 8 + ac;
                float b0 = bias_s[cl], b1 = bias_s[cl + 1];
                float2 v0 = { acc[mi][ni][0] + b0, acc[mi][ni][1] + b1 };
                float2 v1 = { acc[mi][ni][2] + b0, acc[mi][ni][3] + b1 };
                *(float2*)&out[(long)r * H4 + n0 + cl] = v0;
                *(float2*)&out[(long)(r + 8) * H4 + n0 + cl] = v1;
            }
        }
        if (more) { cp_wait0(); __syncthreads(); }
    }
}

// ---------------------------------------------------------------------------
// Encoder recurrent sweep; weights mostly smem-cached (WC=96 k-rows, 192 KB).
// Streamed rows (k>=WC) issued FIRST so their L2 latency overlaps the cached
// section. 147 blocks, 14 used rows (stride 16).
// ---------------------------------------------------------------------------
#define LSTM_SMEM_BYTES ((WC * 512 + 2 * H * TBS) * 4)   // 212,992 B

template <bool WRITE_YS>
__global__ void __launch_bounds__(256, 1) k_lstm_seq(const float4* __restrict__ Wp,
                                                     bf16* __restrict__ ysH,
                                                     bf16* __restrict__ ysL,
                                                     float* __restrict__ hfin,
                                                     float* __restrict__ cfin) {
    extern __shared__ float lsm[];
    float4* wc4 = (float4*)lsm;              // [WC * 128]
    float* h_s = lsm + WC * 512;             // [2][H][TBS]

    const int tid = threadIdx.x;
    const int c = tid & 127, bh = tid >> 7;
    const int b0 = blockIdx.x * TBU;

    int bcl[8];
    bool wr[8];
#pragma unroll
    for (int b = 0; b < 8; ++b) {
        int lb = bh * 8 + b;
        int gb = b0 + lb;
        bcl[b] = gb < BATCH ? gb : BATCH - 1;
        wr[b] = (lb < TBU) && (gb < BATCH);
    }

    // stage cached weights + zero h buffer 1
    for (int i = tid; i < WC * 128; i += 256) wc4[i] = Wp[i];
    for (int i = tid; i < H * TBS; i += 256) h_s[H * TBS + i] = 0.f;
    float c_reg[8] = {0.f, 0.f, 0.f, 0.f, 0.f, 0.f, 0.f, 0.f};
    __syncthreads();

    const float4* wp = Wp + c;
    const float4* wcc = wc4 + c;

#define GATE_BODY(wv)                                                         \
    do {                                                                      \
        ulonglong2 hA = *(const ulonglong2*)(hp + kk * TBS);                  \
        ulonglong2 hB = *(const ulonglong2*)(hp + kk * TBS + 4);              \
        ull w0 = pack2(wv.x, wv.x);                                           \
        ffma2(acc[0][0], w0, hA.x); ffma2(acc[0][1], w0, hA.y);               \
        ffma2(acc[0][2], w0, hB.x); ffma2(acc[0][3], w0, hB.y);               \
        ull w1 = pack2(wv.y, wv.y);                                           \
        ffma2(acc[1][0], w1, hA.x); ffma2(acc[1][1], w1, hA.y);               \
        ffma2(acc[1][2], w1, hB.x); ffma2(acc[1][3], w1, hB.y);               \
        ull w2 = pack2(wv.z, wv.z);                                           \
        ffma2(acc[2][0], w2, hA.x); ffma2(acc[2][1], w2, hA.y);               \
        ffma2(acc[2][2], w2, hB.x); ffma2(acc[2][3], w2, hB.y);               \
        ull w3 = pack2(wv.w, wv.w);                                           \
        ffma2(acc[3][0], w3, hA.x); ffma2(acc[3][1], w3, hA.y);               \
        ffma2(acc[3][2], w3, hB.x); ffma2(acc[3][3], w3, hB.y);               \
    } while (0)

    for (int t = 0; t < SEQ; ++t) {
        const float4* xgt = (const float4*)(g_Xg + (long)t * BATCH * H4) + c;
        float4 xr[8];
#pragma unroll
        for (int b = 0; b < 8; ++b) xr[b] = xgt[(long)bcl[b] * 128];

        ull acc[4][4];
        ull z = pack2(0.f, 0.f);
#pragma unroll
        for (int g = 0; g < 4; ++g)
#pragma unroll
            for (int p = 0; p < 4; ++p) acc[g][p] = z;

        const float* hp = h_s + ((t + 1) & 1) * H * TBS + bh * 8;
        // streamed rows first (L2 latency overlaps cached section below)
#pragma unroll 8
        for (int kk = WC; kk < H; ++kk) {
            float4 w = wp[kk * 128];
            GATE_BODY(w);
        }
#pragma unroll 8
        for (int kk = 0; kk < WC; ++kk) {
            float4 w = wcc[kk * 128];
            GATE_BODY(w);
        }

        float hv[8];
#pragma unroll
        for (int p = 0; p < 4; ++p) {
            float i0, i1, f0, f1, g0, g1, o0, o1;
            unpack2(acc[0][p], i0, i1);
            unpack2(acc[1][p], f0, f1);
            unpack2(acc[2][p], g0, g1);
            unpack2(acc[3][p], o0, o1);
            int b = 2 * p;
            {
                float gi = i0 + xr[b].x, gf = f0 + xr[b].y;
                float gg = g0 + xr[b].z, go = o0 + xr[b].w;
                float cn = sigf(gf) * c_reg[b] + sigf(gi) * tanha(gg);
                c_reg[b] = cn;
                hv[b] = sigf(go) * tanha(cn);
            }
            b = 2 * p + 1;
            {
                float gi = i1 + xr[b].x, gf = f1 + xr[b].y;
                float gg = g1 + xr[b].z, go = o1 + xr[b].w;
                float cn = sigf(gf) * c_reg[b] + sigf(gi) * tanha(gg);
                c_reg[b] = cn;
                hv[b] = sigf(go) * tanha(cn);
            }
        }
        float* hw = h_s + (t & 1) * H * TBS + c * TBS + bh * 8;
        *(float4*)hw       = make_float4(hv[0], hv[1], hv[2], hv[3]);
        *(float4*)(hw + 4) = make_float4(hv[4], hv[5], hv[6], hv[7]);
        if (WRITE_YS) {
            long base_t = (long)t * BATCH * H;
#pragma unroll
            for (int b = 0; b < 8; ++b) {
                if (wr[b]) {
                    bf16 hh, hl;
                    split_bf16(hv[b], hh, hl);
                    long idx = base_t + (long)(b0 + bh * 8 + b) * H + c;
                    ysH[idx] = hh;
                    ysL[idx] = hl;
                }
            }
        }
        __syncthreads();
    }
#pragma unroll
    for (int b = 0; b < 8; ++b) {
        if (wr[b]) {
            hfin[(b0 + bh * 8 + b) * H + c] = h_s[H * TBS + c * TBS + bh * 8 + b];
            cfin[(b0 + bh * 8 + b) * H + c] = c_reg[b];
        }
    }
#undef GATE_BODY
}

// ---------------------------------------------------------------------------
// Fused decoder: 147 blocks, 14 used rows (stride 16). (unchanged)
// ---------------------------------------------------------------------------
#define DSM_H   (NL * 2 * H * TBS)     // 16384 floats
#define DSM_FCW (H * IN_DIM)           // 5632
#define DSM_DIN (IN_DIM * TBS)         // 704
#define DSM_FCB 48
#define DEC_SMEM_BYTES ((DSM_H + DSM_FCW + DSM_DIN + DSM_FCB) * 4)

__global__ void __launch_bounds__(256, 1) k_decoder(const float* __restrict__ x,
                                                    const float* __restrict__ fc_b,
                                                    float* __restrict__ out) {
    extern __shared__ float sm[];
    float* h_s = sm;
    float* fcw = sm + DSM_H;
    float* din = fcw + DSM_FCW;
    float* fcb = din + DSM_DIN;

    const int tid = threadIdx.x;
    const int c = tid & 127, bh = tid >> 7;
    const int b0 = blockIdx.x * TBU;

    for (int i = tid; i < NL * H * TBS; i += 256) {
        int l = i / (H * TBS);
        int r = i - l * (H * TBS);
        int k = r / TBS, b = r - k * TBS;
        int gb = b0 + b; if (gb >= BATCH) gb = BATCH - 1;
        h_s[((l * 2 + 1) * H + k) * TBS + b] = g_h[((long)l * BATCH + gb) * H + k];
    }
    float c_reg[NL * 8];
#pragma unroll
    for (int l = 0; l < NL; ++l)
#pragma unroll
        for (int b = 0; b < 8; ++b) {
            int gb = b0 + bh * 8 + b; if (gb >= BATCH) gb = BATCH - 1;
            c_reg[l * 8 + b] = g_c[((long)l * BATCH + gb) * H + c];
        }
    for (int i = tid; i < DSM_FCW; i += 256) fcw[i] = g_fcT[i];
    for (int i = tid; i < IN_DIM * TBS; i += 256) {
        int k = i >> 4, b = i & 15;
        int gb = b0 + b; if (gb >= BATCH) gb = BATCH - 1;
        din[i] = x[((long)gb * SEQ + (SEQ - 1)) * IN_DIM + k];
    }
    for (int i = tid; i < IN_DIM; i += 256) fcb[i] = fc_b[i];
    __syncthreads();

    float4 bias[NL];
#pragma unroll
    for (int l = 0; l < NL; ++l)
        bias[l] = *(const float4*)&g_decBP[l * H4 + 4 * c];

    for (int t = 0; t < TDEC; ++t) {
        const int cur = t & 1, prv = cur ^ 1;
#pragma unroll 1
        for (int l = 0; l < NL; ++l) {
            ull acc[4][4];
            ull z = pack2(0.f, 0.f);
#pragma unroll
            for (int g = 0; g < 4; ++g)
#pragma unroll
                for (int p = 0; p < 4; ++p) acc[g][p] = z;

            {
                const float4* wr2 = (const float4*)g_decWhhP4 + (long)l * H * H + c;
                const float* hp = &h_s[(l * 2 + prv) * H * TBS + bh * 8];
#pragma unroll 8
                for (int k = 0; k < H; ++k) {
                    float4 w = wr2[k * 128];
                    ulonglong2 hA = *(const ulonglong2*)(hp + k * TBS);
                    ulonglong2 hB = *(const ulonglong2*)(hp + k * TBS + 4);
                    ull w0 = pack2(w.x, w.x);
                    ffma2(acc[0][0], w0, hA.x); ffma2(acc[0][1], w0, hA.y);
                    ffma2(acc[0][2], w0, hB.x); ffma2(acc[0][3], w0, hB.y);
                    ull w1 = pack2(w.y, w.y);
                    ffma2(acc[1][0], w1, hA.x); ffma2(acc[1][1], w1, hA.y);
                    ffma2(acc[1][2], w1, hB.x); ffma2(acc[1][3], w1, hB.y);
                    ull w2 = pack2(w.z, w.z);
                    ffma2(acc[2][0], w2, hA.x); ffma2(acc[2][1], w2, hA.y);
                    ffma2(acc[2][2], w2, hB.x); ffma2(acc[2][3], w2, hB.y);
                    ull w3 = pack2(w.w, w.w);
                    ffma2(acc[3][0], w3, hA.x); ffma2(acc[3][1], w3, hA.y);
                    ffma2(acc[3][2], w3, hB.x); ffma2(acc[3][3], w3, hB.y);
                }
            }
            if (l == 0) {
                const float4* wi = (const float4*)g_decWih0P4 + c;
                const float* dp = din + bh * 8;
#pragma unroll 4
                for (int k = 0; k < IN_DIM; ++k) {
                    float4 w = wi[k * 128];
                    ulonglong2 dA = *(const ulonglong2*)(dp + k * TBS);
                    ulonglong2 dB = *(const ulonglong2*)(dp + k * TBS + 4);
                    ull w0 = pack2(w.x, w.x);
                    ffma2(acc[0][0], w0, dA.x); ffma2(acc[0][1], w0, dA.y);
                    ffma2(acc[0][2], w0, dB.x); ffma2(acc[0][3], w0, dB.y);
                    ull w1 = pack2(w.y, w.y);
                    ffma2(acc[1][0], w1, dA.x); ffma2(acc[1][1], w1, dA.y);
                    ffma2(acc[1][2], w1, dB.x); ffma2(acc[1][3], w1, dB.y);
                    ull w2 = pack2(w.z, w.z);
                    ffma2(acc[2][0], w2, dA.x); ffma2(acc[2][1], w2, dA.y);
                    ffma2(acc[2][2], w2, dB.x); ffma2(acc[2][3], w2, dB.y);
                    ull w3 = pack2(w.w, w.w);
                    ffma2(acc[3][0], w3, dA.x); ffma2(acc[3][1], w3, dA.y);
                    ffma2(acc[3][2], w3, dB.x); ffma2(acc[3][3], w3, dB.y);
                }
            } else {
                const float4* wi = (const float4*)g_decWihRP4 + (long)(l - 1) * H * H + c;
                const float* hp2 = &h_s[((l - 1) * 2 + cur) * H * TBS + bh * 8];
#pragma unroll 8
                for (int k = 0; k < H; ++k) {
                    float4 w = wi[k * 128];
                    ulonglong2 hA = *(const ulonglong2*)(hp2 + k * TBS);
                    ulonglong2 hB = *(const ulonglong2*)(hp2 + k * TBS + 4);
                    ull w0 = pack2(w.x, w.x);
                    ffma2(acc[0][0], w0, hA.x); ffma2(acc[0][1], w0, hA.y);
                    ffma2(acc[0][2], w0, hB.x); ffma2(acc[0][3], w0, hB.y);
                    ull w1 = pack2(w.y, w.y);
                    ffma2(acc[1][0], w1, hA.x); ffma2(acc[1][1], w1, hA.y);
                    ffma2(acc[1][2], w1, hB.x); ffma2(acc[1][3], w1, hB.y);
                    ull w2 = pack2(w.z, w.z);
                    ffma2(acc[2][0], w2, hA.x); ffma2(acc[2][1], w2, hA.y);
                    ffma2(acc[2][2], w2, hB.x); ffma2(acc[2][3], w2, hB.y);
                    ull w3 = pack2(w.w, w.w);
                    ffma2(acc[3][0], w3, hA.x); ffma2(acc[3][1], w3, hA.y);
                    ffma2(acc[3][2], w3, hB.x); ffma2(acc[3][3], w3, hB.y);
                }
            }
            float4 bb = bias[l];
            float hv[8];
#pragma unroll
            for (int p = 0; p < 4; ++p) {
                float i0, i1, f0, f1, g0, g1, o0, o1;
                unpack2(acc[0][p], i0, i1);
                unpack2(acc[1][p], f0, f1);
                unpack2(acc[2][p], g0, g1);
                unpack2(acc[3][p], o0, o1);
                int b = 2 * p;
                {
                    float gi = i0 + bb.x, gf = f0 + bb.y, gg = g0 + bb.z, go = o0 + bb.w;
                    float cn = sigf(gf) * c_reg[l * 8 + b] + sigf(gi) * tanha(gg);
                    c_reg[l * 8 + b] = cn;
                    hv[b] = sigf(go) * tanha(cn);
                }
                b = 2 * p + 1;
                {
                    float gi = i1 + bb.x, gf = f1 + bb.y, gg = g1 + bb.z, go = o1 + bb.w;
                    float cn = sigf(gf) * c_reg[l * 8 + b] + sigf(gi) * tanha(gg);
                    c_reg[l * 8 + b] = cn;
                    hv[b] = sigf(go) * tanha(cn);
                }
            }
            float* hw = &h_s[((l * 2 + cur) * H + c) * TBS + bh * 8];
            *(float4*)hw       = make_float4(hv[0], hv[1], hv[2], hv[3]);
            *(float4*)(hw + 4) = make_float4(hv[4], hv[5], hv[6], hv[7]);
            __syncthreads();
        }
        const float* h3 = &h_s[(3 * 2 + cur) * H * TBS];
        for (int idx = tid; idx < TBS * IN_DIM; idx += 256) {
            int b = idx / IN_DIM, j = idx - b * IN_DIM;
            float s = fcb[j];
#pragma unroll 8
            for (int k = 0; k < H; ++k)
                s += h3[k * TBS + b] * fcw[k * IN_DIM + j];
            if (b < TBU && b0 + b < BATCH)
                out[((long)(b0 + b) * TDEC + t) * IN_DIM + j] = s;
            din[j * TBS + b] = s;
        }
        __syncthreads();
    }
}

// ---------------------------------------------------------------------------
// Host launcher
// ---------------------------------------------------------------------------
extern "C" void kernel_launch(void* const* d_in, const int* in_sizes, int n_in,
                              void* d_out, int out_size) {
    const float* x        = (const float*)d_in[0];
    const float* enc_Wih0 = (const float*)d_in[2];
    const float* enc_WihR = (const float*)d_in[3];
    const float* enc_Whh  = (const float*)d_in[4];
    const float* enc_b    = (const float*)d_in[5];
    const float* dec_Wih0 = (const float*)d_in[6];
    const float* dec_WihR = (const float*)d_in[7];
    const float* dec_Whh  = (const float*)d_in[8];
    const float* dec_b    = (const float*)d_in[9];
    const float* fc_W     = (const float*)d_in[10];
    const float* fc_b     = (const float*)d_in[11];
    float* out = (float*)d_out;

    float *encBP, *decBP;
    float *encWhhP4, *decWhhP4, *decWihRP4, *decWih0P4, *fcT;
    float *Xg, *hSt, *cSt;
    bf16 *W0H, *W0L, *WRH, *WRL, *ysH, *ysL, *x0H, *x0L;
    cudaGetSymbolAddress((void**)&encBP,     g_encBP);
    cudaGetSymbolAddress((void**)&decBP,     g_decBP);
    cudaGetSymbolAddress((void**)&encWhhP4,  g_encWhhP4);
    cudaGetSymbolAddress((void**)&decWhhP4,  g_decWhhP4);
    cudaGetSymbolAddress((void**)&decWihRP4, g_decWihRP4);
    cudaGetSymbolAddress((void**)&decWih0P4, g_decWih0P4);
    cudaGetSymbolAddress((void**)&fcT,       g_fcT);
    cudaGetSymbolAddress((void**)&Xg,        g_Xg);
    cudaGetSymbolAddress((void**)&hSt,       g_h);
    cudaGetSymbolAddress((void**)&cSt,       g_c);
    cudaGetSymbolAddress((void**)&W0H,       g_W0H);
    cudaGetSymbolAddress((void**)&W0L,       g_W0L);
    cudaGetSymbolAddress((void**)&WRH,       g_WRH);
    cudaGetSymbolAddress((void**)&WRL,       g_WRL);
    cudaGetSymbolAddress((void**)&ysH,       g_ysH);
    cudaGetSymbolAddress((void**)&ysL,       g_ysL);
    cudaGetSymbolAddress((void**)&x0H,       g_x0H);
    cudaGetSymbolAddress((void**)&x0L,       g_x0L);

    cudaFuncSetAttribute(k_decoder, cudaFuncAttributeMaxDynamicSharedMemorySize,
                         DEC_SMEM_BYTES);
    const int DYN48  = 2 * (256 * 112) + 4 * (64 * 112) + 1024;   // 87,040
    const int DYN128 = 2 * (256 * 272) + 4 * (64 * 272) + 1024;   // 210,944
    cudaFuncSetAttribute(k_mmagemm<48>,
                         cudaFuncAttributeMaxDynamicSharedMemorySize, DYN48);
    cudaFuncSetAttribute(k_mmagemm<128>,
                         cudaFuncAttributeMaxDynamicSharedMemorySize, DYN128);
    cudaFuncSetAttribute(k_lstm_seq<true>,
                         cudaFuncAttributeMaxDynamicSharedMemorySize, LSTM_SMEM_BYTES);
    cudaFuncSetAttribute(k_lstm_seq<false>,
                         cudaFuncAttributeMaxDynamicSharedMemorySize, LSTM_SMEM_BYTES);

    // prep (3 launches)
    {
        GPJobs jg; jg.n = 12;
        for (int l = 0; l < NL; ++l)
            jg.j[l] = { enc_Whh + (long)l * H4 * H, encWhhP4 + (long)l * H * H * 4, H };
        for (int l = 0; l < NL; ++l)
            jg.j[4 + l] = { dec_Whh + (long)l * H4 * H, decWhhP4 + (long)l * H * H * 4, H };
        for (int r = 0; r < 3; ++r)
            jg.j[8 + r] = { dec_WihR + (long)r * H4 * H, decWihRP4 + (long)r * H * H * 4, H };
        jg.j[11] = { dec_Wih0, decWih0P4, IN_DIM };
        dim3 g(128, 12);
        k_pack4g<<<g, 128>>>(jg);
    }
    {
        dim3 g(256, 5);
        k_wconv<<<g, 256>>>(enc_b, dec_b, fc_W, enc_Wih0, enc_WihR,
                            encBP, decBP, fcT, W0H, W0L, WRH, WRL);
    }
    k_xconv<<<2048, 256>>>(x, x0H, x0L);

    dim3 ggrid(GBX, 2);

    // encoder layer 0
    k_mmagemm<48><<<ggrid, 512, DYN48>>>(x0H, x0L, W0H, W0L, encBP, Xg);
    k_lstm_seq<true><<<RBLK, 256, LSTM_SMEM_BYTES>>>(
        (const float4*)encWhhP4, ysH, ysL, hSt, cSt);
    // encoder layers 1..3
    for (int l = 1; l < NL; ++l) {
        k_mmagemm<128><<<ggrid, 512, DYN128>>>(
            ysH, ysL, WRH + (long)(l - 1) * 512 * 128, WRL + (long)(l - 1) * 512 * 128,
            encBP + (long)l * H4, Xg);
        if (l < NL - 1)
            k_lstm_seq<true><<<RBLK, 256, LSTM_SMEM_BYTES>>>(
                (const float4*)(encWhhP4 + (long)l * H * H * 4), ysH, ysL,
                hSt + (long)l * BATCH * H, cSt + (long)l * BATCH * H);
        else
            k_lstm_seq<false><<<RBLK, 256, LSTM_SMEM_BYTES>>>(
                (const float4*)(encWhhP4 + (long)l * H * H * 4), nullptr, nullptr,
                hSt + (long)l * BATCH * H, cSt + (long)l * BATCH * H);
    }
    // fused decoder
    k_decoder<<<RBLK, 256, DEC_SMEM_BYTES>>>(x, fc_b, out);
}

// round 13
// speedup vs baseline: 1.5459x; 1.4141x over previous
#include <cuda_runtime.h>
#include <cuda_bf16.h>
#include <cstdint>
#include <math.h>

// Problem constants
#define IN_DIM 44
#define H      128
#define H4     512
#define NL     4
#define TDEC   50
#define BATCH  2048
#define SEQ    200

#define TBS 16                       // batch tile stride (smem layout)
#define TBU 14                       // batch rows actually used per block
#define RBLK ((BATCH + TBU - 1) / TBU)   // 147 recurrent/decoder blocks
#define NROWS (SEQ * BATCH)          // 409600 GEMM rows
#define MT64  (NROWS / 64)           // 6400 m-tiles
#define GBX   74                     // GEMM persistent blocks per N-half

typedef unsigned long long ull;
typedef __nv_bfloat16 bf16;

// ---------------------------------------------------------------------------
// Device scratch
// ---------------------------------------------------------------------------
__device__ float g_Xg[(long)NROWS * H4];        // gate-interleaved: [row][4c+g]
__device__ bf16  g_ysH[(long)NROWS * H];        // layer output hi plane [row][k]
__device__ bf16  g_ysL[(long)NROWS * H];        // layer output lo plane
__device__ bf16  g_x0H[(long)NROWS * 48];       // gathered x hi plane [row][48]
__device__ bf16  g_x0L[(long)NROWS * 48];
__device__ float g_h[NL * BATCH * H];
__device__ float g_c[NL * BATCH * H];
// permuted biases [l][4c+g]
__device__ float g_encBP[NL * H4];
__device__ float g_decBP[NL * H4];
// gate-grouped packed recurrent/input weights (decoder): float4[k*128+c]
__device__ float g_decWhhP4[NL * H * H * 4];
__device__ float g_decWihRP4[3 * H * H * 4];
__device__ float g_decWih0P4[IN_DIM * H * 4];
__device__ float g_fcT[H * IN_DIM];
// bf16 hi/lo GEMM weight planes, gate-permuted [n][k] (k padded)
__device__ bf16 g_W0H[512 * 48];
__device__ bf16 g_W0L[512 * 48];
__device__ bf16 g_WRH[3 * 512 * 128];
__device__ bf16 g_WRL[3 * 512 * 128];
// encoder Whh fragment-major bf16 hi/lo planes for mma recurrence:
// per layer: 64 ntiles x 8 ksteps x 32 lanes x 1 ull (2 packed bf16x2)
__device__ ull g_eWhFH[NL * 16384];
__device__ ull g_eWhFL[NL * 16384];

// ---------------------------------------------------------------------------
// packed f32x2 helpers
// ---------------------------------------------------------------------------
__device__ __forceinline__ ull pack2(float a, float b) {
    ull r; asm("mov.b64 %0, {%1,%2};" : "=l"(r) : "f"(a), "f"(b)); return r;
}
__device__ __forceinline__ void unpack2(ull v, float& a, float& b) {
    asm("mov.b64 {%0,%1}, %2;" : "=f"(a), "=f"(b) : "l"(v));
}
__device__ __forceinline__ void ffma2(ull& d, ull a, ull b) {
    asm("fma.rn.f32x2 %0, %1, %2, %0;" : "+l"(d) : "l"(a), "l"(b));
}

// activations via MUFU.TANH
__device__ __forceinline__ float tanha(float x) {
    float y; asm("tanh.approx.f32 %0, %1;" : "=f"(y) : "f"(x)); return y;
}
__device__ __forceinline__ float sigf(float x) {
    return 0.5f * tanha(0.5f * x) + 0.5f;
}

// cp.async helpers
__device__ __forceinline__ void cp16(unsigned int dst, const void* src) {
    asm volatile("cp.async.ca.shared.global [%0], [%1], 16;"
                 :: "r"(dst), "l"(src));
}
__device__ __forceinline__ void cp_commit() {
    asm volatile("cp.async.commit_group;");
}
__device__ __forceinline__ void cp_wait0() {
    asm volatile("cp.async.wait_group 0;");
}

// bf16 mma m16n8k16, f32 accum
#define MMA_BF16(d, a, b)                                                     \
    asm volatile(                                                             \
        "mma.sync.aligned.m16n8k16.row.col.f32.bf16.bf16.f32 "                \
        "{%0,%1,%2,%3}, {%4,%5,%6,%7}, {%8,%9}, {%0,%1,%2,%3};"               \
        : "+f"((d)[0]), "+f"((d)[1]), "+f"((d)[2]), "+f"((d)[3])              \
        : "r"((a)[0]), "r"((a)[1]), "r"((a)[2]), "r"((a)[3]),                 \
          "r"((b)[0]), "r"((b)[1]))

#define LDSM4(r, addr)                                                        \
    asm volatile("ldmatrix.sync.aligned.m8n8.x4.shared.b16 "                  \
        "{%0,%1,%2,%3}, [%4];"                                                \
        : "=r"((r)[0]), "=r"((r)[1]), "=r"((r)[2]), "=r"((r)[3])              \
        : "r"(addr))

__device__ __forceinline__ void split_bf16(float v, bf16& h, bf16& l) {
    h = __float2bfloat16_rn(v);
    l = __float2bfloat16_rn(v - __bfloat162float(h));
}
__device__ __forceinline__ uint32_t pack_bf(float a, float b) {
    __nv_bfloat162 p;
    p.x = __float2bfloat16_rn(a);
    p.y = __float2bfloat16_rn(b);
    return *(uint32_t*)&p;
}

// ---------------------------------------------------------------------------
// Prep kernel 1: gate-grouped 4-pack (decoder only now)
// ---------------------------------------------------------------------------
struct GPJob { const float* s; float* d; int K; };
struct GPJobs { GPJob j[8]; int n; };

__global__ void k_pack4g(GPJobs jobs) {
    int job = blockIdx.y;
    if (job >= jobs.n) return;
    GPJob J = jobs.j[job];
    int i = blockIdx.x * 128 + threadIdx.x;
    if (i < J.K * 128) {
        int k = i >> 7, c = i & 127;
        float4 v;
        v.x = J.s[c * J.K + k];
        v.y = J.s[(128 + c) * J.K + k];
        v.z = J.s[(256 + c) * J.K + k];
        v.w = J.s[(384 + c) * J.K + k];
        ((float4*)J.d)[i] = v;
    }
}

// ---------------------------------------------------------------------------
// Prep kernel 2 (merged): biases/fcT + GEMM weight hi/lo planes
// ---------------------------------------------------------------------------
__global__ void k_wconv(const float* __restrict__ enc_b, const float* __restrict__ dec_b,
                        const float* __restrict__ fc_W,
                        const float* __restrict__ Wih0, const float* __restrict__ WihR,
                        float* __restrict__ encBP, float* __restrict__ decBP,
                        float* __restrict__ fcT,
                        bf16* __restrict__ W0H, bf16* __restrict__ W0L,
                        bf16* __restrict__ WRH, bf16* __restrict__ WRL) {
    int job = blockIdx.y;
    int i = blockIdx.x * 256 + threadIdx.x;
    if (job == 0) {
        if (i < 2048) {
            int l = i >> 9, n = i & 511;
            encBP[i] = enc_b[l * 512 + ((n & 3) * 128 + (n >> 2))];
        } else if (i < 4096) {
            int i2 = i - 2048;
            int l = i2 >> 9, n = i2 & 511;
            decBP[i2] = dec_b[l * 512 + ((n & 3) * 128 + (n >> 2))];
        } else if (i < 4096 + H * IN_DIM) {
            int i2 = i - 4096;
            int k = i2 / IN_DIM, j = i2 - k * IN_DIM;
            fcT[i2] = fc_W[j * H + k];
        }
    } else if (job == 1) {
        if (i < 512 * 48) {
            int n = i / 48, k = i - n * 48;
            float w = 0.f;
            if (k < IN_DIM) w = Wih0[((n & 3) * 128 + (n >> 2)) * IN_DIM + k];
            split_bf16(w, W0H[i], W0L[i]);
        }
    } else {
        int r = job - 2;
        if (i < 512 * 128) {
            int n = i >> 7, k = i & 127;
            float w = WihR[(long)r * 512 * 128 + ((n & 3) * 128 + (n >> 2)) * 128 + k];
            split_bf16(w, WRH[(long)r * 512 * 128 + i], WRL[(long)r * 512 * 128 + i]);
        }
    }
}

// ---------------------------------------------------------------------------
// Prep kernel 3: gather x -> hi/lo bf16 [row][48]
// ---------------------------------------------------------------------------
__global__ void k_xconv(const float* __restrict__ x,
                        bf16* __restrict__ XH, bf16* __restrict__ XL) {
    for (long i = (long)blockIdx.x * 256 + threadIdx.x; i < (long)NROWS * 48;
         i += (long)gridDim.x * 256) {
        int row = (int)(i / 48), k = (int)(i - (long)row * 48);
        int t = row >> 11, b = row & 2047;
        float v = (k < IN_DIM) ? x[((long)b * SEQ + t) * IN_DIM + k] : 0.f;
        split_bf16(v, XH[i], XL[i]);
    }
}

// ---------------------------------------------------------------------------
// Prep kernel 4: encoder Whh -> fragment-major bf16 hi/lo planes.
// u32 entry e (per layer): fi = e>>1, j = e&1; lane = fi&31, s = (fi>>5)&7,
// T = fi>>8; n = T*8 + (lane>>2); k = s*16 + (lane&3)*2 + j*8.
// value = pack(bf16 W(n,k), bf16 W(n,k+1)); W(n,k) = Whh[(n&3)*128+(n>>2)][k].
// ---------------------------------------------------------------------------
__global__ void k_bfrag(const float* __restrict__ Whh,
                        ull* __restrict__ FH, ull* __restrict__ FL) {
    int u = blockIdx.x * 256 + threadIdx.x;        // [0, 4*32768)
    if (u >= NL * 32768) return;
    int l = u >> 15, e = u & 32767;
    int fi = e >> 1, j = e & 1;
    int lane = fi & 31, s = (fi >> 5) & 7, T = fi >> 8;
    int n = T * 8 + (lane >> 2);
    int k = s * 16 + (lane & 3) * 2 + j * 8;
    const float* W = Whh + (long)l * 512 * 128;
    int row = (n & 3) * 128 + (n >> 2);
    float v0 = W[row * 128 + k];
    float v1 = W[row * 128 + k + 1];
    bf16 h0, l0, h1, l1;
    split_bf16(v0, h0, l0);
    split_bf16(v1, h1, l1);
    __nv_bfloat162 ph; ph.x = h0; ph.y = h1;
    __nv_bfloat162 pl; pl.x = l0; pl.y = l1;
    ((uint32_t*)(FH + (long)l * 16384))[e] = *(uint32_t*)&ph;
    ((uint32_t*)(FL + (long)l * 16384))[e] = *(uint32_t*)&pl;
}

// ---------------------------------------------------------------------------
// Persistent weight-resident split-bf16 tensor-core GEMM (ldmatrix, 512 thr).
// (unchanged from R12)
// ---------------------------------------------------------------------------
template <int K>
__global__ void __launch_bounds__(512, 1)
k_mmagemm(const bf16* __restrict__ AH, const bf16* __restrict__ AL,
          const bf16* __restrict__ WH, const bf16* __restrict__ WL,
          const float* __restrict__ biasP, float* __restrict__ out) {
    extern __shared__ char smc[];
    const int KSTEPS = K / 16;
    const int ROWB = (K + 8) * 2;
    const int BSP  = 256 * ROWB;
    const int ASP2 = 64 * ROWB;
    const int CPR  = K / 8;

    char* Bb = smc;
    char* Ab = smc + 2 * BSP;
    float* bias_s = (float*)(smc + 2 * BSP + 4 * ASP2);

    const int tid = threadIdx.x;
    const int n0 = blockIdx.y * 256;
    const int w = tid >> 5, lane = tid & 31;
    const int wm = w >> 3, wn = w & 7;
    const int ar = lane >> 2, ac = (lane & 3) * 2;
    const int li = lane & 7, lq = lane >> 3;
    const int aoff = (li + (lq & 1) * 8) * ROWB + (lq >> 1) * 16;
    const int boff = (li + (lq >> 1) * 8) * ROWB + (lq & 1) * 16;

    const unsigned Bb_s = (unsigned)__cvta_generic_to_shared(Bb);
    const unsigned Ab_s = (unsigned)__cvta_generic_to_shared(Ab);

    if (tid < 256) bias_s[tid] = biasP[n0 + tid];

    {
        const int total = 2 * 256 * CPR;
        for (int i = tid; i < total; i += 512) {
            int split = i / (256 * CPR);
            int rem = i - split * 256 * CPR;
            int n = rem / CPR, ch = rem - n * CPR;
            const bf16* src = (split ? WL : WH) + (long)(n0 + n) * K + ch * 8;
            unsigned dst = (unsigned)__cvta_generic_to_shared(
                Bb + split * BSP + n * ROWB + ch * 16);
            cp16(dst, src);
        }
        cp_commit();
    }

    auto issueA = [&](int mt, int buf) {
        const int total = 2 * 64 * CPR;
        for (int i = tid; i < total; i += 512) {
            int split = i / (64 * CPR);
            int rem = i - split * 64 * CPR;
            int row = rem / CPR, ch = rem - row * CPR;
            const bf16* src = (split ? AL : AH) + (long)(mt * 64 + row) * K + ch * 8;
            unsigned dst = (unsigned)__cvta_generic_to_shared(
                Ab + buf * 2 * ASP2 + split * ASP2 + row * ROWB + ch * 16);
            cp16(dst, src);
        }
        cp_commit();
    };

    issueA(blockIdx.x, 0);
    cp_wait0();
    __syncthreads();

    int it = 0;
    for (int mt = blockIdx.x; mt < MT64; mt += GBX, ++it) {
        const int buf = it & 1;
        const bool more = (mt + GBX < MT64);
        if (more) issueA(mt + GBX, buf ^ 1);

        const unsigned Ahb = Ab_s + buf * 2 * ASP2;

        float acc[2][4][4];
#pragma unroll
        for (int mi = 0; mi < 2; ++mi)
#pragma unroll
            for (int ni = 0; ni < 4; ++ni)
#pragma unroll
                for (int q = 0; q < 4; ++q) acc[mi][ni][q] = 0.f;

#pragma unroll
        for (int ks = 0; ks < KSTEPS; ++ks) {
            const int kb2 = ks * 32;
            uint32_t ah[2][4], al[2][4];
#pragma unroll
            for (int mi = 0; mi < 2; ++mi) {
                unsigned base = Ahb + (wm * 32 + mi * 16) * ROWB + kb2 + aoff;
                LDSM4(ah[mi], base);
                LDSM4(al[mi], base + ASP2);
            }
            uint32_t bhf[2][4], blf[2][4];
#pragma unroll
            for (int p = 0; p < 2; ++p) {
                unsigned nb = Bb_s + (wn * 32 + p * 16) * ROWB + kb2 + boff;
                LDSM4(bhf[p], nb);
                LDSM4(blf[p], nb + BSP);
            }
#pragma unroll
            for (int p = 0; p < 2; ++p) {
#pragma unroll
                for (int hh = 0; hh < 2; ++hh) {
                    int ni = p * 2 + hh;
                    uint32_t* bH = &bhf[p][hh * 2];
                    uint32_t* bL = &blf[p][hh * 2];
                    MMA_BF16(acc[0][ni], ah[0], bH);
                    MMA_BF16(acc[1][ni], ah[1], bH);
                    MMA_BF16(acc[0][ni], ah[0], bL);
                    MMA_BF16(acc[1][ni], ah[1], bL);
                    MMA_BF16(acc[0][ni], al[0], bH);
                    MMA_BF16(acc[1][ni], al[1], bH);
                }
            }
        }

        const int m0 = mt * 64;
#pragma unroll
        for (int mi = 0; mi < 2; ++mi) {
            int r = m0 + wm * 32 + mi * 16 + ar;
#pragma unroll
            for (int ni = 0; ni < 4; ++ni) {
                int cl = wn * 32 + ni * 8 + ac;
                float b0 = bias_s[cl], b1 = bias_s[cl + 1];
                float2 v0 = { acc[mi][ni][0] + b0, acc[mi][ni][1] + b1 };
                float2 v1 = { acc[mi][ni][2] + b0, acc[mi][ni][3] + b1 };
                *(float2*)&out[(long)r * H4 + n0 + cl] = v0;
                *(float2*)&out[(long)(r + 8) * H4 + n0 + cl] = v1;
            }
        }
        if (more) { cp_wait0(); __syncthreads(); }
    }
}

// ---------------------------------------------------------------------------
// Tensor-core encoder recurrence. Block = 8 warps, M=16 batch (TBU=14 used),
// N=512 gates. Bhi frag-major in smem (LDS.64), Blo frag-major gmem (LDG.64,
// L1-resident), h double-buffered bf16 hi/lo smem planes (ldmatrix A).
// Warp w owns gate cols [64w,64w+64) == cell cols [16w,16w+16): gates exchange
// is warp-private (syncwarp); ONE block barrier per step.
// ---------------------------------------------------------------------------
#define AROWB 272
#define ASPL  (16 * AROWB)            // 4352 B per A plane
#define BFRAG_BYTES 131072
#define GST   520
#define LSTM_MMA_SMEM (BFRAG_BYTES + 4 * ASPL + 16 * GST * 4)   // 181,760 B

template <bool WRITE_YS>
__global__ void __launch_bounds__(256, 1)
k_lstm_mma(const ull* __restrict__ FH, const ull* __restrict__ FL,
           bf16* __restrict__ ysH, bf16* __restrict__ ysL,
           float* __restrict__ hfin, float* __restrict__ cfin) {
    extern __shared__ char smc[];
    ull* BhF = (ull*)smc;                       // 16384 ull
    char* As = smc + BFRAG_BYTES;               // [2 buf][2 split][16][AROWB]
    float* gates = (float*)(As + 4 * ASPL);     // [16][GST]

    const int tid = threadIdx.x;
    const int w = tid >> 5, lane = tid & 31;
    const int li = lane & 7, lq = lane >> 3;
    const int aoff = (li + (lq & 1) * 8) * AROWB + (lq >> 1) * 16;
    const int ar = lane >> 2, ac = (lane & 3) * 2;
    const int cc = w * 16 + (lane & 15);
    const int hb = lane >> 4;
    const int b0 = blockIdx.x * TBU;

    // stage Bhi frags; zero A buf0 (both planes)
    for (int i = tid; i < 16384; i += 256) BhF[i] = FH[i];
    for (int i = tid; i < 2 * ASPL / 4; i += 256) ((float*)As)[i] = 0.f;

    float c_reg[8], hlast[8];
    int gbc[8]; bool vld[8];
#pragma unroll
    for (int i = 0; i < 8; ++i) {
        c_reg[i] = 0.f; hlast[i] = 0.f;
        int b = hb * 8 + i;
        int gb = b0 + b;
        gbc[i] = gb < BATCH ? gb : BATCH - 1;
        vld[i] = (b < TBU) && (gb < BATCH);
    }
    __syncthreads();

    const unsigned As_s = (unsigned)__cvta_generic_to_shared(As);

    for (int t = 0; t < SEQ; ++t) {
        // prefetch Xg (gate-interleaved float4 per (b, cc))
        float4 xr[8];
        const float* xg = g_Xg + (long)t * BATCH * H4 + 4 * cc;
#pragma unroll
        for (int i = 0; i < 8; ++i) xr[i] = *(const float4*)(xg + (long)gbc[i] * H4);

        const unsigned Ab = As_s + (t & 1) * (2 * ASPL);
        float acc[8][4];
#pragma unroll
        for (int ni = 0; ni < 8; ++ni)
#pragma unroll
            for (int q = 0; q < 4; ++q) acc[ni][q] = 0.f;

#pragma unroll
        for (int s = 0; s < 8; ++s) {
            uint32_t ah[4], al[4];
            LDSM4(ah, Ab + s * 32 + aoff);
            LDSM4(al, Ab + ASPL + s * 32 + aoff);
#pragma unroll
            for (int ni = 0; ni < 8; ++ni) {
                int fi = ((w * 8 + ni) * 8 + s) * 32 + lane;
                ull bh8 = BhF[fi];
                ull bl8 = FL[fi];
                uint32_t bh[2] = { (uint32_t)bh8, (uint32_t)(bh8 >> 32) };
                uint32_t bl[2] = { (uint32_t)bl8, (uint32_t)(bl8 >> 32) };
                MMA_BF16(acc[ni], ah, bh);
                MMA_BF16(acc[ni], ah, bl);
                MMA_BF16(acc[ni], al, bh);
            }
        }
        // write gates to warp-private smem region
#pragma unroll
        for (int ni = 0; ni < 8; ++ni) {
            int n0 = w * 64 + ni * 8 + ac;
            float2 v0 = { acc[ni][0], acc[ni][1] };
            float2 v1 = { acc[ni][2], acc[ni][3] };
            *(float2*)&gates[ar * GST + n0] = v0;
            *(float2*)&gates[(ar + 8) * GST + n0] = v1;
        }
        __syncwarp();
        // cell phase (thread owns col cc x 8 batch rows)
        char* An = As + (((t + 1) & 1)) * (2 * ASPL);
#pragma unroll
        for (int i = 0; i < 8; ++i) {
            int b = hb * 8 + i;
            float4 g4 = *(const float4*)&gates[b * GST + 4 * cc];
            float gi = g4.x + xr[i].x, gf = g4.y + xr[i].y;
            float gg = g4.z + xr[i].z, go = g4.w + xr[i].w;
            float cn = sigf(gf) * c_reg[i] + sigf(gi) * tanha(gg);
            c_reg[i] = cn;
            float hn = sigf(go) * tanha(cn);
            hlast[i] = hn;
            bf16 hh, hl;
            split_bf16(hn, hh, hl);
            *(bf16*)(An + b * AROWB + cc * 2) = hh;
            *(bf16*)(An + ASPL + b * AROWB + cc * 2) = hl;
            if (WRITE_YS && vld[i]) {
                long idx = ((long)t * BATCH + b0 + b) * H + cc;
                ysH[idx] = hh;
                ysL[idx] = hl;
            }
        }
        __syncthreads();
    }
#pragma unroll
    for (int i = 0; i < 8; ++i) {
        if (vld[i]) {
            long gb = b0 + hb * 8 + i;
            hfin[gb * H + cc] = hlast[i];
            cfin[gb * H + cc] = c_reg[i];
        }
    }
}

// ---------------------------------------------------------------------------
// Fused decoder (unchanged from R12)
// ---------------------------------------------------------------------------
#define DSM_H   (NL * 2 * H * TBS)
#define DSM_FCW (H * IN_DIM)
#define DSM_DIN (IN_DIM * TBS)
#define DSM_FCB 48
#define DEC_SMEM_BYTES ((DSM_H + DSM_FCW + DSM_DIN + DSM_FCB) * 4)

__global__ void __launch_bounds__(256, 1) k_decoder(const float* __restrict__ x,
                                                    const float* __restrict__ fc_b,
                                                    float* __restrict__ out) {
    extern __shared__ float sm[];
    float* h_s = sm;
    float* fcw = sm + DSM_H;
    float* din = fcw + DSM_FCW;
    float* fcb = din + DSM_DIN;

    const int tid = threadIdx.x;
    const int c = tid & 127, bh = tid >> 7;
    const int b0 = blockIdx.x * TBU;

    for (int i = tid; i < NL * H * TBS; i += 256) {
        int l = i / (H * TBS);
        int r = i - l * (H * TBS);
        int k = r / TBS, b = r - k * TBS;
        int gb = b0 + b; if (gb >= BATCH) gb = BATCH - 1;
        h_s[((l * 2 + 1) * H + k) * TBS + b] = g_h[((long)l * BATCH + gb) * H + k];
    }
    float c_reg[NL * 8];
#pragma unroll
    for (int l = 0; l < NL; ++l)
#pragma unroll
        for (int b = 0; b < 8; ++b) {
            int gb = b0 + bh * 8 + b; if (gb >= BATCH) gb = BATCH - 1;
            c_reg[l * 8 + b] = g_c[((long)l * BATCH + gb) * H + c];
        }
    for (int i = tid; i < DSM_FCW; i += 256) fcw[i] = g_fcT[i];
    for (int i = tid; i < IN_DIM * TBS; i += 256) {
        int k = i >> 4, b = i & 15;
        int gb = b0 + b; if (gb >= BATCH) gb = BATCH - 1;
        din[i] = x[((long)gb * SEQ + (SEQ - 1)) * IN_DIM + k];
    }
    for (int i = tid; i < IN_DIM; i += 256) fcb[i] = fc_b[i];
    __syncthreads();

    float4 bias[NL];
#pragma unroll
    for (int l = 0; l < NL; ++l)
        bias[l] = *(const float4*)&g_decBP[l * H4 + 4 * c];

    for (int t = 0; t < TDEC; ++t) {
        const int cur = t & 1, prv = cur ^ 1;
#pragma unroll 1
        for (int l = 0; l < NL; ++l) {
            ull acc[4][4];
            ull z = pack2(0.f, 0.f);
#pragma unroll
            for (int g = 0; g < 4; ++g)
#pragma unroll
                for (int p = 0; p < 4; ++p) acc[g][p] = z;

            {
                const float4* wr2 = (const float4*)g_decWhhP4 + (long)l * H * H + c;
                const float* hp = &h_s[(l * 2 + prv) * H * TBS + bh * 8];
#pragma unroll 8
                for (int k = 0; k < H; ++k) {
                    float4 w = wr2[k * 128];
                    ulonglong2 hA = *(const ulonglong2*)(hp + k * TBS);
                    ulonglong2 hB = *(const ulonglong2*)(hp + k * TBS + 4);
                    ull w0 = pack2(w.x, w.x);
                    ffma2(acc[0][0], w0, hA.x); ffma2(acc[0][1], w0, hA.y);
                    ffma2(acc[0][2], w0, hB.x); ffma2(acc[0][3], w0, hB.y);
                    ull w1 = pack2(w.y, w.y);
                    ffma2(acc[1][0], w1, hA.x); ffma2(acc[1][1], w1, hA.y);
                    ffma2(acc[1][2], w1, hB.x); ffma2(acc[1][3], w1, hB.y);
                    ull w2 = pack2(w.z, w.z);
                    ffma2(acc[2][0], w2, hA.x); ffma2(acc[2][1], w2, hA.y);
                    ffma2(acc[2][2], w2, hB.x); ffma2(acc[2][3], w2, hB.y);
                    ull w3 = pack2(w.w, w.w);
                    ffma2(acc[3][0], w3, hA.x); ffma2(acc[3][1], w3, hA.y);
                    ffma2(acc[3][2], w3, hB.x); ffma2(acc[3][3], w3, hB.y);
                }
            }
            if (l == 0) {
                const float4* wi = (const float4*)g_decWih0P4 + c;
                const float* dp = din + bh * 8;
#pragma unroll 4
                for (int k = 0; k < IN_DIM; ++k) {
                    float4 w = wi[k * 128];
                    ulonglong2 dA = *(const ulonglong2*)(dp + k * TBS);
                    ulonglong2 dB = *(const ulonglong2*)(dp + k * TBS + 4);
                    ull w0 = pack2(w.x, w.x);
                    ffma2(acc[0][0], w0, dA.x); ffma2(acc[0][1], w0, dA.y);
                    ffma2(acc[0][2], w0, dB.x); ffma2(acc[0][3], w0, dB.y);
                    ull w1 = pack2(w.y, w.y);
                    ffma2(acc[1][0], w1, dA.x); ffma2(acc[1][1], w1, dA.y);
                    ffma2(acc[1][2], w1, dB.x); ffma2(acc[1][3], w1, dB.y);
                    ull w2 = pack2(w.z, w.z);
                    ffma2(acc[2][0], w2, dA.x); ffma2(acc[2][1], w2, dA.y);
                    ffma2(acc[2][2], w2, dB.x); ffma2(acc[2][3], w2, dB.y);
                    ull w3 = pack2(w.w, w.w);
                    ffma2(acc[3][0], w3, dA.x); ffma2(acc[3][1], w3, dA.y);
                    ffma2(acc[3][2], w3, dB.x); ffma2(acc[3][3], w3, dB.y);
                }
            } else {
                const float4* wi = (const float4*)g_decWihRP4 + (long)(l - 1) * H * H + c;
                const float* hp2 = &h_s[((l - 1) * 2 + cur) * H * TBS + bh * 8];
#pragma unroll 8
                for (int k = 0; k < H; ++k) {
                    float4 w = wi[k * 128];
                    ulonglong2 hA = *(const ulonglong2*)(hp2 + k * TBS);
                    ulonglong2 hB = *(const ulonglong2*)(hp2 + k * TBS + 4);
                    ull w0 = pack2(w.x, w.x);
                    ffma2(acc[0][0], w0, hA.x); ffma2(acc[0][1], w0, hA.y);
                    ffma2(acc[0][2], w0, hB.x); ffma2(acc[0][3], w0, hB.y);
                    ull w1 = pack2(w.y, w.y);
                    ffma2(acc[1][0], w1, hA.x); ffma2(acc[1][1], w1, hA.y);
                    ffma2(acc[1][2], w1, hB.x); ffma2(acc[1][3], w1, hB.y);
                    ull w2 = pack2(w.z, w.z);
                    ffma2(acc[2][0], w2, hA.x); ffma2(acc[2][1], w2, hA.y);
                    ffma2(acc[2][2], w2, hB.x); ffma2(acc[2][3], w2, hB.y);
                    ull w3 = pack2(w.w, w.w);
                    ffma2(acc[3][0], w3, hA.x); ffma2(acc[3][1], w3, hA.y);
                    ffma2(acc[3][2], w3, hB.x); ffma2(acc[3][3], w3, hB.y);
                }
            }
            float4 bb = bias[l];
            float hv[8];
#pragma unroll
            for (int p = 0; p < 4; ++p) {
                float i0, i1, f0, f1, g0, g1, o0, o1;
                unpack2(acc[0][p], i0, i1);
                unpack2(acc[1][p], f0, f1);
                unpack2(acc[2][p], g0, g1);
                unpack2(acc[3][p], o0, o1);
                int b = 2 * p;
                {
                    float gi = i0 + bb.x, gf = f0 + bb.y, gg = g0 + bb.z, go = o0 + bb.w;
                    float cn = sigf(gf) * c_reg[l * 8 + b] + sigf(gi) * tanha(gg);
                    c_reg[l * 8 + b] = cn;
                    hv[b] = sigf(go) * tanha(cn);
                }
                b = 2 * p + 1;
                {
                    float gi = i1 + bb.x, gf = f1 + bb.y, gg = g1 + bb.z, go = o1 + bb.w;
                    float cn = sigf(gf) * c_reg[l * 8 + b] + sigf(gi) * tanha(gg);
                    c_reg[l * 8 + b] = cn;
                    hv[b] = sigf(go) * tanha(cn);
                }
            }
            float* hw = &h_s[((l * 2 + cur) * H + c) * TBS + bh * 8];
            *(float4*)hw       = make_float4(hv[0], hv[1], hv[2], hv[3]);
            *(float4*)(hw + 4) = make_float4(hv[4], hv[5], hv[6], hv[7]);
            __syncthreads();
        }
        const float* h3 = &h_s[(3 * 2 + cur) * H * TBS];
        for (int idx = tid; idx < TBS * IN_DIM; idx += 256) {
            int b = idx / IN_DIM, j = idx - b * IN_DIM;
            float s = fcb[j];
#pragma unroll 8
            for (int k = 0; k < H; ++k)
                s += h3[k * TBS + b] * fcw[k * IN_DIM + j];
            if (b < TBU && b0 + b < BATCH)
                out[((long)(b0 + b) * TDEC + t) * IN_DIM + j] = s;
            din[j * TBS + b] = s;
        }
        __syncthreads();
    }
}

// ---------------------------------------------------------------------------
// Host launcher
// ---------------------------------------------------------------------------
extern "C" void kernel_launch(void* const* d_in, const int* in_sizes, int n_in,
                              void* d_out, int out_size) {
    const float* x        = (const float*)d_in[0];
    const float* enc_Wih0 = (const float*)d_in[2];
    const float* enc_WihR = (const float*)d_in[3];
    const float* enc_Whh  = (const float*)d_in[4];
    const float* enc_b    = (const float*)d_in[5];
    const float* dec_Wih0 = (const float*)d_in[6];
    const float* dec_WihR = (const float*)d_in[7];
    const float* dec_Whh  = (const float*)d_in[8];
    const float* dec_b    = (const float*)d_in[9];
    const float* fc_W     = (const float*)d_in[10];
    const float* fc_b     = (const float*)d_in[11];
    float* out = (float*)d_out;

    float *encBP, *decBP;
    float *decWhhP4, *decWihRP4, *decWih0P4, *fcT;
    float *Xg, *hSt, *cSt;
    bf16 *W0H, *W0L, *WRH, *WRL, *ysH, *ysL, *x0H, *x0L;
    ull *eFH, *eFL;
    cudaGetSymbolAddress((void**)&encBP,     g_encBP);
    cudaGetSymbolAddress((void**)&decBP,     g_decBP);
    cudaGetSymbolAddress((void**)&decWhhP4,  g_decWhhP4);
    cudaGetSymbolAddress((void**)&decWihRP4, g_decWihRP4);
    cudaGetSymbolAddress((void**)&decWih0P4, g_decWih0P4);
    cudaGetSymbolAddress((void**)&fcT,       g_fcT);
    cudaGetSymbolAddress((void**)&Xg,        g_Xg);
    cudaGetSymbolAddress((void**)&hSt,       g_h);
    cudaGetSymbolAddress((void**)&cSt,       g_c);
    cudaGetSymbolAddress((void**)&W0H,       g_W0H);
    cudaGetSymbolAddress((void**)&W0L,       g_W0L);
    cudaGetSymbolAddress((void**)&WRH,       g_WRH);
    cudaGetSymbolAddress((void**)&WRL,       g_WRL);
    cudaGetSymbolAddress((void**)&ysH,       g_ysH);
    cudaGetSymbolAddress((void**)&ysL,       g_ysL);
    cudaGetSymbolAddress((void**)&x0H,       g_x0H);
    cudaGetSymbolAddress((void**)&x0L,       g_x0L);
    cudaGetSymbolAddress((void**)&eFH,       g_eWhFH);
    cudaGetSymbolAddress((void**)&eFL,       g_eWhFL);

    cudaFuncSetAttribute(k_decoder, cudaFuncAttributeMaxDynamicSharedMemorySize,
                         DEC_SMEM_BYTES);
    const int DYN48  = 2 * (256 * 112) + 4 * (64 * 112) + 1024;
    const int DYN128 = 2 * (256 * 272) + 4 * (64 * 272) + 1024;
    cudaFuncSetAttribute(k_mmagemm<48>,
                         cudaFuncAttributeMaxDynamicSharedMemorySize, DYN48);
    cudaFuncSetAttribute(k_mmagemm<128>,
                         cudaFuncAttributeMaxDynamicSharedMemorySize, DYN128);
    cudaFuncSetAttribute(k_lstm_mma<true>,
                         cudaFuncAttributeMaxDynamicSharedMemorySize, LSTM_MMA_SMEM);
    cudaFuncSetAttribute(k_lstm_mma<false>,
                         cudaFuncAttributeMaxDynamicSharedMemorySize, LSTM_MMA_SMEM);

    // prep (4 launches)
    {
        GPJobs jg; jg.n = 8;
        for (int l = 0; l < NL; ++l)
            jg.j[l] = { dec_Whh + (long)l * H4 * H, decWhhP4 + (long)l * H * H * 4, H };
        for (int r = 0; r < 3; ++r)
            jg.j[4 + r] = { dec_WihR + (long)r * H4 * H, decWihRP4 + (long)r * H * H * 4, H };
        jg.j[7] = { dec_Wih0, decWih0P4, IN_DIM };
        dim3 g(128, 8);
        k_pack4g<<<g, 128>>>(jg);
    }
    {
        dim3 g(256, 5);
        k_wconv<<<g, 256>>>(enc_b, dec_b, fc_W, enc_Wih0, enc_WihR,
                            encBP, decBP, fcT, W0H, W0L, WRH, WRL);
    }
    k_bfrag<<<(NL * 32768 + 255) / 256, 256>>>(enc_Whh, eFH, eFL);
    k_xconv<<<2048, 256>>>(x, x0H, x0L);

    dim3 ggrid(GBX, 2);

    // encoder layer 0
    k_mmagemm<48><<<ggrid, 512, DYN48>>>(x0H, x0L, W0H, W0L, encBP, Xg);
    k_lstm_mma<true><<<RBLK, 256, LSTM_MMA_SMEM>>>(eFH, eFL, ysH, ysL, hSt, cSt);
    // encoder layers 1..3
    for (int l = 1; l < NL; ++l) {
        k_mmagemm<128><<<ggrid, 512, DYN128>>>(
            ysH, ysL, WRH + (long)(l - 1) * 512 * 128, WRL + (long)(l - 1) * 512 * 128,
            encBP + (long)l * H4, Xg);
        if (l < NL - 1)
            k_lstm_mma<true><<<RBLK, 256, LSTM_MMA_SMEM>>>(
                eFH + (long)l * 16384, eFL + (long)l * 16384, ysH, ysL,
                hSt + (long)l * BATCH * H, cSt + (long)l * BATCH * H);
        else
            k_lstm_mma<false><<<RBLK, 256, LSTM_MMA_SMEM>>>(
                eFH + (long)l * 16384, eFL + (long)l * 16384, nullptr, nullptr,
                hSt + (long)l * BATCH * H, cSt + (long)l * BATCH * H);
    }
    // fused decoder
    k_decoder<<<RBLK, 256, DEC_SMEM_BYTES>>>(x, fc_b, out);
}

// round 14
// speedup vs baseline: 2.0469x; 1.3241x over previous
#include <cuda_runtime.h>
#include <cuda_bf16.h>
#include <cstdint>
#include <math.h>

// Problem constants
#define IN_DIM 44
#define H      128
#define H4     512
#define NL     4
#define TDEC   50
#define BATCH  2048
#define SEQ    200

#define TBS 16                       // batch tile stride
#define TBU 14                       // batch rows used per block
#define RBLK ((BATCH + TBU - 1) / TBU)   // 147 blocks
#define NROWS (SEQ * BATCH)
#define MT64  (NROWS / 64)
#define GBX   74

typedef unsigned long long ull;
typedef __nv_bfloat16 bf16;

// ---------------------------------------------------------------------------
// Device scratch
// ---------------------------------------------------------------------------
__device__ float g_Xg[(long)NROWS * H4];
__device__ bf16  g_ysH[(long)NROWS * H];
__device__ bf16  g_ysL[(long)NROWS * H];
__device__ bf16  g_x0H[(long)NROWS * 48];
__device__ bf16  g_x0L[(long)NROWS * 48];
__device__ float g_h[NL * BATCH * H];
__device__ float g_c[NL * BATCH * H];
__device__ float g_encBP[NL * H4];
__device__ float g_decBP[NL * H4];
__device__ float g_fcT[H * IN_DIM];
// bf16 hi/lo GEMM weight planes, gate-permuted [n][k]
__device__ bf16 g_W0H[512 * 48];
__device__ bf16 g_W0L[512 * 48];
__device__ bf16 g_WRH[3 * 512 * 128];
__device__ bf16 g_WRL[3 * 512 * 128];
// fragment-major bf16 hi/lo weight planes for mma recurrences
__device__ ull g_eWhFH[NL * 16384];
__device__ ull g_eWhFL[NL * 16384];
__device__ ull g_dWhFH[NL * 16384];
__device__ ull g_dWhFL[NL * 16384];
__device__ ull g_dWiFH[3 * 16384];
__device__ ull g_dWiFL[3 * 16384];
__device__ ull g_dWi0FH[6144];
__device__ ull g_dWi0FL[6144];

// ---------------------------------------------------------------------------
// helpers
// ---------------------------------------------------------------------------
__device__ __forceinline__ float tanha(float x) {
    float y; asm("tanh.approx.f32 %0, %1;" : "=f"(y) : "f"(x)); return y;
}
__device__ __forceinline__ float sigf(float x) {
    return 0.5f * tanha(0.5f * x) + 0.5f;
}

__device__ __forceinline__ void cp16(unsigned int dst, const void* src) {
    asm volatile("cp.async.ca.shared.global [%0], [%1], 16;"
                 :: "r"(dst), "l"(src));
}
__device__ __forceinline__ void cp_commit() {
    asm volatile("cp.async.commit_group;");
}
__device__ __forceinline__ void cp_wait0() {
    asm volatile("cp.async.wait_group 0;");
}

#define MMA_BF16(d, a, b)                                                     \
    asm volatile(                                                             \
        "mma.sync.aligned.m16n8k16.row.col.f32.bf16.bf16.f32 "                \
        "{%0,%1,%2,%3}, {%4,%5,%6,%7}, {%8,%9}, {%0,%1,%2,%3};"               \
        : "+f"((d)[0]), "+f"((d)[1]), "+f"((d)[2]), "+f"((d)[3])              \
        : "r"((a)[0]), "r"((a)[1]), "r"((a)[2]), "r"((a)[3]),                 \
          "r"((b)[0]), "r"((b)[1]))

#define LDSM4(r, addr)                                                        \
    asm volatile("ldmatrix.sync.aligned.m8n8.x4.shared.b16 "                  \
        "{%0,%1,%2,%3}, [%4];"                                                \
        : "=r"((r)[0]), "=r"((r)[1]), "=r"((r)[2]), "=r"((r)[3])              \
        : "r"(addr))

__device__ __forceinline__ void split_bf16(float v, bf16& h, bf16& l) {
    h = __float2bfloat16_rn(v);
    l = __float2bfloat16_rn(v - __bfloat162float(h));
}

// ---------------------------------------------------------------------------
// Prep kernel A (merged): biases/fcT + GEMM weight hi/lo planes
// ---------------------------------------------------------------------------
__global__ void k_wconv(const float* __restrict__ enc_b, const float* __restrict__ dec_b,
                        const float* __restrict__ fc_W,
                        const float* __restrict__ Wih0, const float* __restrict__ WihR,
                        float* __restrict__ encBP, float* __restrict__ decBP,
                        float* __restrict__ fcT,
                        bf16* __restrict__ W0H, bf16* __restrict__ W0L,
                        bf16* __restrict__ WRH, bf16* __restrict__ WRL) {
    int job = blockIdx.y;
    int i = blockIdx.x * 256 + threadIdx.x;
    if (job == 0) {
        if (i < 2048) {
            int l = i >> 9, n = i & 511;
            encBP[i] = enc_b[l * 512 + ((n & 3) * 128 + (n >> 2))];
        } else if (i < 4096) {
            int i2 = i - 2048;
            int l = i2 >> 9, n = i2 & 511;
            decBP[i2] = dec_b[l * 512 + ((n & 3) * 128 + (n >> 2))];
        } else if (i < 4096 + H * IN_DIM) {
            int i2 = i - 4096;
            int k = i2 / IN_DIM, j = i2 - k * IN_DIM;
            fcT[i2] = fc_W[j * H + k];
        }
    } else if (job == 1) {
        if (i < 512 * 48) {
            int n = i / 48, k = i - n * 48;
            float w = 0.f;
            if (k < IN_DIM) w = Wih0[((n & 3) * 128 + (n >> 2)) * IN_DIM + k];
            split_bf16(w, W0H[i], W0L[i]);
        }
    } else {
        int r = job - 2;
        if (i < 512 * 128) {
            int n = i >> 7, k = i & 127;
            float w = WihR[(long)r * 512 * 128 + ((n & 3) * 128 + (n >> 2)) * 128 + k];
            split_bf16(w, WRH[(long)r * 512 * 128 + i], WRL[(long)r * 512 * 128 + i]);
        }
    }
}

// ---------------------------------------------------------------------------
// Prep kernel B: gather x -> hi/lo bf16 [row][48]
// ---------------------------------------------------------------------------
__global__ void k_xconv(const float* __restrict__ x,
                        bf16* __restrict__ XH, bf16* __restrict__ XL) {
    for (long i = (long)blockIdx.x * 256 + threadIdx.x; i < (long)NROWS * 48;
         i += (long)gridDim.x * 256) {
        int row = (int)(i / 48), k = (int)(i - (long)row * 48);
        int t = row >> 11, b = row & 2047;
        float v = (k < IN_DIM) ? x[((long)b * SEQ + t) * IN_DIM + k] : 0.f;
        split_bf16(v, XH[i], XL[i]);
    }
}

// ---------------------------------------------------------------------------
// Prep kernel C: generalized fragment builder.
// entry e (u32): fi=e>>1, j=e&1; lane=fi&31; rest=fi>>5; s=rest%ksteps;
// T=rest/ksteps; n=T*8+(lane>>2); k=s*16+(lane&3)*2+j*8;
// value = pack(bf16 W(n,k), bf16 W(n,k+1)); W row = (n&3)*128+(n>>2), stride ksrc.
// ---------------------------------------------------------------------------
struct FJob { const float* s; ull* fh; ull* fl; int ksteps; int ksrc; };
struct FJobs { FJob j[12]; int n; };

__global__ void k_fragb(FJobs jobs) {
    int job = blockIdx.y;
    if (job >= jobs.n) return;
    FJob J = jobs.j[job];
    int e = blockIdx.x * 256 + threadIdx.x;
    int tot = 64 * J.ksteps * 32 * 2;
    if (e >= tot) return;
    int fi = e >> 1, jj = e & 1;
    int lane = fi & 31;
    int rest = fi >> 5;
    int s = rest % J.ksteps;
    int T = rest / J.ksteps;
    int n = T * 8 + (lane >> 2);
    int k = s * 16 + (lane & 3) * 2 + jj * 8;
    int row = (n & 3) * 128 + (n >> 2);
    float v0 = (k < J.ksrc) ? J.s[(long)row * J.ksrc + k] : 0.f;
    float v1 = (k + 1 < J.ksrc) ? J.s[(long)row * J.ksrc + k + 1] : 0.f;
    bf16 h0, l0, h1, l1;
    split_bf16(v0, h0, l0);
    split_bf16(v1, h1, l1);
    __nv_bfloat162 ph; ph.x = h0; ph.y = h1;
    __nv_bfloat162 pl; pl.x = l0; pl.y = l1;
    ((uint32_t*)J.fh)[e] = *(uint32_t*)&ph;
    ((uint32_t*)J.fl)[e] = *(uint32_t*)&pl;
}

// ---------------------------------------------------------------------------
// Persistent weight-resident split-bf16 tensor-core GEMM (unchanged)
// ---------------------------------------------------------------------------
template <int K>
__global__ void __launch_bounds__(512, 1)
k_mmagemm(const bf16* __restrict__ AH, const bf16* __restrict__ AL,
          const bf16* __restrict__ WH, const bf16* __restrict__ WL,
          const float* __restrict__ biasP, float* __restrict__ out) {
    extern __shared__ char smc[];
    const int KSTEPS = K / 16;
    const int ROWB = (K + 8) * 2;
    const int BSP  = 256 * ROWB;
    const int ASP2 = 64 * ROWB;
    const int CPR  = K / 8;

    char* Bb = smc;
    char* Ab = smc + 2 * BSP;
    float* bias_s = (float*)(smc + 2 * BSP + 4 * ASP2);

    const int tid = threadIdx.x;
    const int n0 = blockIdx.y * 256;
    const int w = tid >> 5, lane = tid & 31;
    const int wm = w >> 3, wn = w & 7;
    const int ar = lane >> 2, ac = (lane & 3) * 2;
    const int li = lane & 7, lq = lane >> 3;
    const int aoff = (li + (lq & 1) * 8) * ROWB + (lq >> 1) * 16;
    const int boff = (li + (lq >> 1) * 8) * ROWB + (lq & 1) * 16;

    const unsigned Bb_s = (unsigned)__cvta_generic_to_shared(Bb);
    const unsigned Ab_s = (unsigned)__cvta_generic_to_shared(Ab);

    if (tid < 256) bias_s[tid] = biasP[n0 + tid];

    {
        const int total = 2 * 256 * CPR;
        for (int i = tid; i < total; i += 512) {
            int split = i / (256 * CPR);
            int rem = i - split * 256 * CPR;
            int n = rem / CPR, ch = rem - n * CPR;
            const bf16* src = (split ? WL : WH) + (long)(n0 + n) * K + ch * 8;
            unsigned dst = (unsigned)__cvta_generic_to_shared(
                Bb + split * BSP + n * ROWB + ch * 16);
            cp16(dst, src);
        }
        cp_commit();
    }

    auto issueA = [&](int mt, int buf) {
        const int total = 2 * 64 * CPR;
        for (int i = tid; i < total; i += 512) {
            int split = i / (64 * CPR);
            int rem = i - split * 64 * CPR;
            int row = rem / CPR, ch = rem - row * CPR;
            const bf16* src = (split ? AL : AH) + (long)(mt * 64 + row) * K + ch * 8;
            unsigned dst = (unsigned)__cvta_generic_to_shared(
                Ab + buf * 2 * ASP2 + split * ASP2 + row * ROWB + ch * 16);
            cp16(dst, src);
        }
        cp_commit();
    };

    issueA(blockIdx.x, 0);
    cp_wait0();
    __syncthreads();

    int it = 0;
    for (int mt = blockIdx.x; mt < MT64; mt += GBX, ++it) {
        const int buf = it & 1;
        const bool more = (mt + GBX < MT64);
        if (more) issueA(mt + GBX, buf ^ 1);

        const unsigned Ahb = Ab_s + buf * 2 * ASP2;

        float acc[2][4][4];
#pragma unroll
        for (int mi = 0; mi < 2; ++mi)
#pragma unroll
            for (int ni = 0; ni < 4; ++ni)
#pragma unroll
                for (int q = 0; q < 4; ++q) acc[mi][ni][q] = 0.f;

#pragma unroll
        for (int ks = 0; ks < KSTEPS; ++ks) {
            const int kb2 = ks * 32;
            uint32_t ah[2][4], al[2][4];
#pragma unroll
            for (int mi = 0; mi < 2; ++mi) {
                unsigned base = Ahb + (wm * 32 + mi * 16) * ROWB + kb2 + aoff;
                LDSM4(ah[mi], base);
                LDSM4(al[mi], base + ASP2);
            }
            uint32_t bhf[2][4], blf[2][4];
#pragma unroll
            for (int p = 0; p < 2; ++p) {
                unsigned nb = Bb_s + (wn * 32 + p * 16) * ROWB + kb2 + boff;
                LDSM4(bhf[p], nb);
                LDSM4(blf[p], nb + BSP);
            }
#pragma unroll
            for (int p = 0; p < 2; ++p) {
#pragma unroll
                for (int hh = 0; hh < 2; ++hh) {
                    int ni = p * 2 + hh;
                    uint32_t* bH = &bhf[p][hh * 2];
                    uint32_t* bL = &blf[p][hh * 2];
                    MMA_BF16(acc[0][ni], ah[0], bH);
                    MMA_BF16(acc[1][ni], ah[1], bH);
                    MMA_BF16(acc[0][ni], ah[0], bL);
                    MMA_BF16(acc[1][ni], ah[1], bL);
                    MMA_BF16(acc[0][ni], al[0], bH);
                    MMA_BF16(acc[1][ni], al[1], bH);
                }
            }
        }

        const int m0 = mt * 64;
#pragma unroll
        for (int mi = 0; mi < 2; ++mi) {
            int r = m0 + wm * 32 + mi * 16 + ar;
#pragma unroll
            for (int ni = 0; ni < 4; ++ni) {
                int cl = wn * 32 + ni * 8 + ac;
                float b0 = bias_s[cl], b1 = bias_s[cl + 1];
                float2 v0 = { acc[mi][ni][0] + b0, acc[mi][ni][1] + b1 };
                float2 v1 = { acc[mi][ni][2] + b0, acc[mi][ni][3] + b1 };
                *(float2*)&out[(long)r * H4 + n0 + cl] = v0;
                *(float2*)&out[(long)(r + 8) * H4 + n0 + cl] = v1;
            }
        }
        if (more) { cp_wait0(); __syncthreads(); }
    }
}

// ---------------------------------------------------------------------------
// Tensor-core encoder recurrence (unchanged from R13)
// ---------------------------------------------------------------------------
#define AROWB 272
#define ASPL  (16 * AROWB)
#define BFRAG_BYTES 131072
#define GST   520
#define LSTM_MMA_SMEM (BFRAG_BYTES + 4 * ASPL + 16 * GST * 4)

template <bool WRITE_YS>
__global__ void __launch_bounds__(256, 1)
k_lstm_mma(const ull* __restrict__ FH, const ull* __restrict__ FL,
           bf16* __restrict__ ysH, bf16* __restrict__ ysL,
           float* __restrict__ hfin, float* __restrict__ cfin) {
    extern __shared__ char smc[];
    ull* BhF = (ull*)smc;
    char* As = smc + BFRAG_BYTES;
    float* gates = (float*)(As + 4 * ASPL);

    const int tid = threadIdx.x;
    const int w = tid >> 5, lane = tid & 31;
    const int li = lane & 7, lq = lane >> 3;
    const int aoff = (li + (lq & 1) * 8) * AROWB + (lq >> 1) * 16;
    const int ar = lane >> 2, ac = (lane & 3) * 2;
    const int cc = w * 16 + (lane & 15);
    const int hb = lane >> 4;
    const int b0 = blockIdx.x * TBU;

    for (int i = tid; i < 16384; i += 256) BhF[i] = FH[i];
    for (int i = tid; i < 2 * ASPL / 4; i += 256) ((float*)As)[i] = 0.f;

    float c_reg[8], hlast[8];
    int gbc[8]; bool vld[8];
#pragma unroll
    for (int i = 0; i < 8; ++i) {
        c_reg[i] = 0.f; hlast[i] = 0.f;
        int b = hb * 8 + i;
        int gb = b0 + b;
        gbc[i] = gb < BATCH ? gb : BATCH - 1;
        vld[i] = (b < TBU) && (gb < BATCH);
    }
    __syncthreads();

    const unsigned As_s = (unsigned)__cvta_generic_to_shared(As);

    for (int t = 0; t < SEQ; ++t) {
        float4 xr[8];
        const float* xg = g_Xg + (long)t * BATCH * H4 + 4 * cc;
#pragma unroll
        for (int i = 0; i < 8; ++i) xr[i] = *(const float4*)(xg + (long)gbc[i] * H4);

        const unsigned Ab = As_s + (t & 1) * (2 * ASPL);
        float acc[8][4];
#pragma unroll
        for (int ni = 0; ni < 8; ++ni)
#pragma unroll
            for (int q = 0; q < 4; ++q) acc[ni][q] = 0.f;

#pragma unroll
        for (int s = 0; s < 8; ++s) {
            uint32_t ah[4], al[4];
            LDSM4(ah, Ab + s * 32 + aoff);
            LDSM4(al, Ab + ASPL + s * 32 + aoff);
#pragma unroll
            for (int ni = 0; ni < 8; ++ni) {
                int fi = ((w * 8 + ni) * 8 + s) * 32 + lane;
                ull bh8 = BhF[fi];
                ull bl8 = FL[fi];
                uint32_t bh[2] = { (uint32_t)bh8, (uint32_t)(bh8 >> 32) };
                uint32_t bl[2] = { (uint32_t)bl8, (uint32_t)(bl8 >> 32) };
                MMA_BF16(acc[ni], ah, bh);
                MMA_BF16(acc[ni], ah, bl);
                MMA_BF16(acc[ni], al, bh);
            }
        }
#pragma unroll
        for (int ni = 0; ni < 8; ++ni) {
            int n0 = w * 64 + ni * 8 + ac;
            float2 v0 = { acc[ni][0], acc[ni][1] };
            float2 v1 = { acc[ni][2], acc[ni][3] };
            *(float2*)&gates[ar * GST + n0] = v0;
            *(float2*)&gates[(ar + 8) * GST + n0] = v1;
        }
        __syncwarp();
        char* An = As + (((t + 1) & 1)) * (2 * ASPL);
#pragma unroll
        for (int i = 0; i < 8; ++i) {
            int b = hb * 8 + i;
            float4 g4 = *(const float4*)&gates[b * GST + 4 * cc];
            float gi = g4.x + xr[i].x, gf = g4.y + xr[i].y;
            float gg = g4.z + xr[i].z, go = g4.w + xr[i].w;
            float cn = sigf(gf) * c_reg[i] + sigf(gi) * tanha(gg);
            c_reg[i] = cn;
            float hn = sigf(go) * tanha(cn);
            hlast[i] = hn;
            bf16 hh, hl;
            split_bf16(hn, hh, hl);
            *(bf16*)(An + b * AROWB + cc * 2) = hh;
            *(bf16*)(An + ASPL + b * AROWB + cc * 2) = hl;
            if (WRITE_YS && vld[i]) {
                long idx = ((long)t * BATCH + b0 + b) * H + cc;
                ysH[idx] = hh;
                ysL[idx] = hl;
            }
        }
        __syncthreads();
    }
#pragma unroll
    for (int i = 0; i < 8; ++i) {
        if (vld[i]) {
            long gb = b0 + hb * 8 + i;
            hfin[gb * H + cc] = hlast[i];
            cfin[gb * H + cc] = c_reg[i];
        }
    }
}

// ---------------------------------------------------------------------------
// Tensor-core fused decoder. Block = 8 warps, M=16 (TBU=14 used). Per layer:
// gates = h_l(t-1) @ WhhF + input @ WiF (MMA, 3-term split); cell in regs.
// h per layer as bf16 hi/lo A-planes in smem; din (fc feedback) as K=48 A
// buffer; fc over fp32 h3 shadow. Frags streamed from gmem (L2 resident).
// ---------------------------------------------------------------------------
#define DIROWB 112
#define DISPL  (16 * DIROWB)          // 1792
#define DEC_MMA_SMEM (NL * 2 * ASPL + 2 * DISPL + 16 * GST * 4 + 2048 * 4 + DSMFCW * 4 + 192)
#define DSMFCW (H * IN_DIM)

__global__ void __launch_bounds__(256, 1)
k_decoder_mma(const float* __restrict__ x, const float* __restrict__ fc_b,
              const ull* __restrict__ WhFH, const ull* __restrict__ WhFL,
              const ull* __restrict__ WiFH, const ull* __restrict__ WiFL,
              const ull* __restrict__ Wi0FH, const ull* __restrict__ Wi0FL,
              float* __restrict__ out) {
    extern __shared__ char smc[];
    char* hbuf = smc;                               // [l][plane][ASPL]
    char* dinb = smc + NL * 2 * ASPL;               // [plane][DISPL]
    float* gates = (float*)(dinb + 2 * DISPL);      // [16][GST]
    float* fcH = gates + 16 * GST;                  // [128][16] fp32 h3
    float* fcw = fcH + 2048;
    float* fcb = fcw + DSMFCW;

    const int tid = threadIdx.x;
    const int w = tid >> 5, lane = tid & 31;
    const int li = lane & 7, lq = lane >> 3;
    const int aoff  = (li + (lq & 1) * 8) * AROWB + (lq >> 1) * 16;
    const int aoff2 = (li + (lq & 1) * 8) * DIROWB + (lq >> 1) * 16;
    const int ar = lane >> 2, ac = (lane & 3) * 2;
    const int cc = w * 16 + (lane & 15);
    const int hbi = lane >> 4;
    const int b0 = blockIdx.x * TBU;

    int gbc[8]; bool vld[8];
#pragma unroll
    for (int i = 0; i < 8; ++i) {
        int b = hbi * 8 + i;
        int gb = b0 + b;
        gbc[i] = gb < BATCH ? gb : BATCH - 1;
        vld[i] = (b < TBU) && (gb < BATCH);
    }
    float c_reg[NL][8];
#pragma unroll
    for (int l = 0; l < NL; ++l)
#pragma unroll
        for (int i = 0; i < 8; ++i) {
            c_reg[l][i] = g_c[((long)l * BATCH + gbc[i]) * H + cc];
            float hv = g_h[((long)l * BATCH + gbc[i]) * H + cc];
            bf16 hh, hl;
            split_bf16(hv, hh, hl);
            int b = hbi * 8 + i;
            char* hb = hbuf + l * 2 * ASPL;
            *(bf16*)(hb + b * AROWB + cc * 2) = hh;
            *(bf16*)(hb + ASPL + b * AROWB + cc * 2) = hl;
        }
    // din init: last x timestep, K padded to 48
    for (int i = tid; i < 16 * 48; i += 256) {
        int b = i / 48, j = i - b * 48;
        int gb = b0 + b; if (gb >= BATCH) gb = BATCH - 1;
        float v = (j < IN_DIM) ? x[((long)gb * SEQ + (SEQ - 1)) * IN_DIM + j] : 0.f;
        bf16 hh, hl;
        split_bf16(v, hh, hl);
        *(bf16*)(dinb + b * DIROWB + j * 2) = hh;
        *(bf16*)(dinb + DISPL + b * DIROWB + j * 2) = hl;
    }
    for (int i = tid; i < DSMFCW; i += 256) fcw[i] = g_fcT[i];
    for (int i = tid; i < IN_DIM; i += 256) fcb[i] = fc_b[i];

    float4 bias[NL];
#pragma unroll
    for (int l = 0; l < NL; ++l)
        bias[l] = *(const float4*)&g_decBP[l * H4 + 4 * cc];
    __syncthreads();

    const unsigned hb_s = (unsigned)__cvta_generic_to_shared(hbuf);
    const unsigned di_s = (unsigned)__cvta_generic_to_shared(dinb);

    for (int t = 0; t < TDEC; ++t) {
#pragma unroll 1
        for (int l = 0; l < NL; ++l) {
            float acc[8][4];
#pragma unroll
            for (int ni = 0; ni < 8; ++ni)
#pragma unroll
                for (int q = 0; q < 4; ++q) acc[ni][q] = 0.f;

            // recurrent: A = h_l(t-1)
            {
                const unsigned AbH = hb_s + l * 2 * ASPL;
                const ull* FH = WhFH + (long)l * 16384;
                const ull* FL = WhFL + (long)l * 16384;
#pragma unroll
                for (int s = 0; s < 8; ++s) {
                    uint32_t ah[4], al[4];
                    LDSM4(ah, AbH + s * 32 + aoff);
                    LDSM4(al, AbH + ASPL + s * 32 + aoff);
#pragma unroll
                    for (int ni = 0; ni < 8; ++ni) {
                        int fi = ((w * 8 + ni) * 8 + s) * 32 + lane;
                        ull bh8 = FH[fi];
                        ull bl8 = FL[fi];
                        uint32_t bh[2] = { (uint32_t)bh8, (uint32_t)(bh8 >> 32) };
                        uint32_t bl[2] = { (uint32_t)bl8, (uint32_t)(bl8 >> 32) };
                        MMA_BF16(acc[ni], ah, bh);
                        MMA_BF16(acc[ni], ah, bl);
                        MMA_BF16(acc[ni], al, bh);
                    }
                }
            }
            // input: l==0 -> din (K=48); l>0 -> h_{l-1}(t)
            if (l == 0) {
#pragma unroll
                for (int s = 0; s < 3; ++s) {
                    uint32_t ah[4], al[4];
                    LDSM4(ah, di_s + s * 32 + aoff2);
                    LDSM4(al, di_s + DISPL + s * 32 + aoff2);
#pragma unroll
                    for (int ni = 0; ni < 8; ++ni) {
                        int fi = ((w * 8 + ni) * 3 + s) * 32 + lane;
                        ull bh8 = Wi0FH[fi];
                        ull bl8 = Wi0FL[fi];
                        uint32_t bh[2] = { (uint32_t)bh8, (uint32_t)(bh8 >> 32) };
                        uint32_t bl[2] = { (uint32_t)bl8, (uint32_t)(bl8 >> 32) };
                        MMA_BF16(acc[ni], ah, bh);
                        MMA_BF16(acc[ni], ah, bl);
                        MMA_BF16(acc[ni], al, bh);
                    }
                }
            } else {
                const unsigned AbH = hb_s + (l - 1) * 2 * ASPL;
                const ull* FH = WiFH + (long)(l - 1) * 16384;
                const ull* FL = WiFL + (long)(l - 1) * 16384;
#pragma unroll
                for (int s = 0; s < 8; ++s) {
                    uint32_t ah[4], al[4];
                    LDSM4(ah, AbH + s * 32 + aoff);
                    LDSM4(al, AbH + ASPL + s * 32 + aoff);
#pragma unroll
                    for (int ni = 0; ni < 8; ++ni) {
                        int fi = ((w * 8 + ni) * 8 + s) * 32 + lane;
                        ull bh8 = FH[fi];
                        ull bl8 = FL[fi];
                        uint32_t bh[2] = { (uint32_t)bh8, (uint32_t)(bh8 >> 32) };
                        uint32_t bl[2] = { (uint32_t)bl8, (uint32_t)(bl8 >> 32) };
                        MMA_BF16(acc[ni], ah, bh);
                        MMA_BF16(acc[ni], ah, bl);
                        MMA_BF16(acc[ni], al, bh);
                    }
                }
            }
            // gates exchange (warp-private cols)
#pragma unroll
            for (int ni = 0; ni < 8; ++ni) {
                int n0 = w * 64 + ni * 8 + ac;
                float2 v0 = { acc[ni][0], acc[ni][1] };
                float2 v1 = { acc[ni][2], acc[ni][3] };
                *(float2*)&gates[ar * GST + n0] = v0;
                *(float2*)&gates[(ar + 8) * GST + n0] = v1;
            }
            __syncwarp();
            // cell phase
            char* hb = hbuf + l * 2 * ASPL;
#pragma unroll
            for (int i = 0; i < 8; ++i) {
                int b = hbi * 8 + i;
                float4 g4 = *(const float4*)&gates[b * GST + 4 * cc];
                float gi = g4.x + bias[l].x, gf = g4.y + bias[l].y;
                float gg = g4.z + bias[l].z, go = g4.w + bias[l].w;
                float cn = sigf(gf) * c_reg[l][i] + sigf(gi) * tanha(gg);
                c_reg[l][i] = cn;
                float hn = sigf(go) * tanha(cn);
                bf16 hh, hl;
                split_bf16(hn, hh, hl);
                *(bf16*)(hb + b * AROWB + cc * 2) = hh;
                *(bf16*)(hb + ASPL + b * AROWB + cc * 2) = hl;
                if (l == NL - 1) fcH[cc * 16 + b] = hn;
            }
            __syncthreads();
        }
        // fc: out = h3 @ fcT + fc_b; feeds din
        for (int idx = tid; idx < 16 * IN_DIM; idx += 256) {
            int b = idx / IN_DIM, j = idx - b * IN_DIM;
            float s = fcb[j];
#pragma unroll 8
            for (int k = 0; k < H; ++k)
                s += fcH[k * 16 + b] * fcw[k * IN_DIM + j];
            if (b < TBU && b0 + b < BATCH)
                out[((long)(b0 + b) * TDEC + t) * IN_DIM + j] = s;
            bf16 hh, hl;
            split_bf16(s, hh, hl);
            *(bf16*)(dinb + b * DIROWB + j * 2) = hh;
            *(bf16*)(dinb + DISPL + b * DIROWB + j * 2) = hl;
        }
        __syncthreads();
    }
}

// ---------------------------------------------------------------------------
// Host launcher
// ---------------------------------------------------------------------------
extern "C" void kernel_launch(void* const* d_in, const int* in_sizes, int n_in,
                              void* d_out, int out_size) {
    const float* x        = (const float*)d_in[0];
    const float* enc_Wih0 = (const float*)d_in[2];
    const float* enc_WihR = (const float*)d_in[3];
    const float* enc_Whh  = (const float*)d_in[4];
    const float* enc_b    = (const float*)d_in[5];
    const float* dec_Wih0 = (const float*)d_in[6];
    const float* dec_WihR = (const float*)d_in[7];
    const float* dec_Whh  = (const float*)d_in[8];
    const float* dec_b    = (const float*)d_in[9];
    const float* fc_W     = (const float*)d_in[10];
    const float* fc_b     = (const float*)d_in[11];
    float* out = (float*)d_out;

    float *encBP, *decBP, *fcT, *Xg, *hSt, *cSt;
    bf16 *W0H, *W0L, *WRH, *WRL, *ysH, *ysL, *x0H, *x0L;
    ull *eFH, *eFL, *dWhH, *dWhL, *dWiH, *dWiL, *dWi0H, *dWi0L;
    cudaGetSymbolAddress((void**)&encBP, g_encBP);
    cudaGetSymbolAddress((void**)&decBP, g_decBP);
    cudaGetSymbolAddress((void**)&fcT,   g_fcT);
    cudaGetSymbolAddress((void**)&Xg,    g_Xg);
    cudaGetSymbolAddress((void**)&hSt,   g_h);
    cudaGetSymbolAddress((void**)&cSt,   g_c);
    cudaGetSymbolAddress((void**)&W0H,   g_W0H);
    cudaGetSymbolAddress((void**)&W0L,   g_W0L);
    cudaGetSymbolAddress((void**)&WRH,   g_WRH);
    cudaGetSymbolAddress((void**)&WRL,   g_WRL);
    cudaGetSymbolAddress((void**)&ysH,   g_ysH);
    cudaGetSymbolAddress((void**)&ysL,   g_ysL);
    cudaGetSymbolAddress((void**)&x0H,   g_x0H);
    cudaGetSymbolAddress((void**)&x0L,   g_x0L);
    cudaGetSymbolAddress((void**)&eFH,   g_eWhFH);
    cudaGetSymbolAddress((void**)&eFL,   g_eWhFL);
    cudaGetSymbolAddress((void**)&dWhH,  g_dWhFH);
    cudaGetSymbolAddress((void**)&dWhL,  g_dWhFL);
    cudaGetSymbolAddress((void**)&dWiH,  g_dWiFH);
    cudaGetSymbolAddress((void**)&dWiL,  g_dWiFL);
    cudaGetSymbolAddress((void**)&dWi0H, g_dWi0FH);
    cudaGetSymbolAddress((void**)&dWi0L, g_dWi0FL);

    const int DYN48  = 2 * (256 * 112) + 4 * (64 * 112) + 1024;
    const int DYN128 = 2 * (256 * 272) + 4 * (64 * 272) + 1024;
    const int DECSM = NL * 2 * ASPL + 2 * DISPL + 16 * GST * 4 + 2048 * 4
                    + DSMFCW * 4 + 192;
    cudaFuncSetAttribute(k_mmagemm<48>,
                         cudaFuncAttributeMaxDynamicSharedMemorySize, DYN48);
    cudaFuncSetAttribute(k_mmagemm<128>,
                         cudaFuncAttributeMaxDynamicSharedMemorySize, DYN128);
    cudaFuncSetAttribute(k_lstm_mma<true>,
                         cudaFuncAttributeMaxDynamicSharedMemorySize, LSTM_MMA_SMEM);
    cudaFuncSetAttribute(k_lstm_mma<false>,
                         cudaFuncAttributeMaxDynamicSharedMemorySize, LSTM_MMA_SMEM);
    cudaFuncSetAttribute(k_decoder_mma,
                         cudaFuncAttributeMaxDynamicSharedMemorySize, DECSM);

    // prep (3 launches)
    {
        dim3 g(256, 5);
        k_wconv<<<g, 256>>>(enc_b, dec_b, fc_W, enc_Wih0, enc_WihR,
                            encBP, decBP, fcT, W0H, W0L, WRH, WRL);
    }
    {
        FJobs jf; jf.n = 12;
        for (int l = 0; l < NL; ++l)
            jf.j[l] = { enc_Whh + (long)l * 512 * 128, eFH + (long)l * 16384,
                        eFL + (long)l * 16384, 8, 128 };
        for (int l = 0; l < NL; ++l)
            jf.j[4 + l] = { dec_Whh + (long)l * 512 * 128, dWhH + (long)l * 16384,
                            dWhL + (long)l * 16384, 8, 128 };
        for (int r = 0; r < 3; ++r)
            jf.j[8 + r] = { dec_WihR + (long)r * 512 * 128, dWiH + (long)r * 16384,
                            dWiL + (long)r * 16384, 8, 128 };
        jf.j[11] = { dec_Wih0, dWi0H, dWi0L, 3, IN_DIM };
        dim3 g(128, 12);
        k_fragb<<<g, 256>>>(jf);
    }
    k_xconv<<<2048, 256>>>(x, x0H, x0L);

    dim3 ggrid(GBX, 2);

    // encoder layer 0
    k_mmagemm<48><<<ggrid, 512, DYN48>>>(x0H, x0L, W0H, W0L, encBP, Xg);
    k_lstm_mma<true><<<RBLK, 256, LSTM_MMA_SMEM>>>(eFH, eFL, ysH, ysL, hSt, cSt);
    // encoder layers 1..3
    for (int l = 1; l < NL; ++l) {
        k_mmagemm<128><<<ggrid, 512, DYN128>>>(
            ysH, ysL, WRH + (long)(l - 1) * 512 * 128, WRL + (long)(l - 1) * 512 * 128,
            encBP + (long)l * H4, Xg);
        if (l < NL - 1)
            k_lstm_mma<true><<<RBLK, 256, LSTM_MMA_SMEM>>>(
                eFH + (long)l * 16384, eFL + (long)l * 16384, ysH, ysL,
                hSt + (long)l * BATCH * H, cSt + (long)l * BATCH * H);
        else
            k_lstm_mma<false><<<RBLK, 256, LSTM_MMA_SMEM>>>(
                eFH + (long)l * 16384, eFL + (long)l * 16384, nullptr, nullptr,
                hSt + (long)l * BATCH * H, cSt + (long)l * BATCH * H);
    }
    // tensor-core fused decoder
    k_decoder_mma<<<RBLK, 256, DECSM>>>(x, fc_b, dWhH, dWhL, dWiH, dWiL,
                                        dWi0H, dWi0L, out);
}

// round 15
// speedup vs baseline: 2.0565x; 1.0047x over previous
#include <cuda_runtime.h>
#include <cuda_bf16.h>
#include <cstdint>
#include <math.h>

// Problem constants
#define IN_DIM 44
#define H      128
#define H4     512
#define NL     4
#define TDEC   50
#define BATCH  2048
#define SEQ    200

#define TBS 16                       // batch tile stride
#define TBU 14                       // batch rows used per block
#define RBLK ((BATCH + TBU - 1) / TBU)   // 147 blocks
#define NROWS (SEQ * BATCH)
#define MT64  (NROWS / 64)
#define GBX   74

typedef unsigned long long ull;
typedef __nv_bfloat16 bf16;

// ---------------------------------------------------------------------------
// Device scratch
// ---------------------------------------------------------------------------
__device__ float g_Xg[(long)NROWS * H4];
__device__ bf16  g_ysH[(long)NROWS * H];
__device__ bf16  g_ysL[(long)NROWS * H];
__device__ bf16  g_x0H[(long)NROWS * 48];
__device__ bf16  g_x0L[(long)NROWS * 48];
__device__ float g_h[NL * BATCH * H];
__device__ float g_c[NL * BATCH * H];
__device__ float g_encBP[NL * H4];
__device__ float g_decBP[NL * H4];
__device__ float g_fcT[H * IN_DIM];
// bf16 hi/lo GEMM weight planes, gate-permuted [n][k]
__device__ bf16 g_W0H[512 * 48];
__device__ bf16 g_W0L[512 * 48];
__device__ bf16 g_WRH[3 * 512 * 128];
__device__ bf16 g_WRL[3 * 512 * 128];
// fragment-major bf16 hi/lo weight planes for mma recurrences
__device__ ull g_eWhFH[NL * 16384];
__device__ ull g_eWhFL[NL * 16384];
__device__ ull g_dWhFH[NL * 16384];
__device__ ull g_dWhFL[NL * 16384];
__device__ ull g_dWiFH[3 * 16384];
__device__ ull g_dWiFL[3 * 16384];
__device__ ull g_dWi0FH[6144];
__device__ ull g_dWi0FL[6144];

// ---------------------------------------------------------------------------
// helpers
// ---------------------------------------------------------------------------
__device__ __forceinline__ float tanha(float x) {
    float y; asm("tanh.approx.f32 %0, %1;" : "=f"(y) : "f"(x)); return y;
}
__device__ __forceinline__ float sigf(float x) {
    return 0.5f * tanha(0.5f * x) + 0.5f;
}

__device__ __forceinline__ void cp16(unsigned int dst, const void* src) {
    asm volatile("cp.async.ca.shared.global [%0], [%1], 16;"
                 :: "r"(dst), "l"(src));
}
__device__ __forceinline__ void cp_commit() {
    asm volatile("cp.async.commit_group;");
}
__device__ __forceinline__ void cp_wait0() {
    asm volatile("cp.async.wait_group 0;");
}

#define MMA_BF16(d, a, b)                                                     \
    asm volatile(                                                             \
        "mma.sync.aligned.m16n8k16.row.col.f32.bf16.bf16.f32 "                \
        "{%0,%1,%2,%3}, {%4,%5,%6,%7}, {%8,%9}, {%0,%1,%2,%3};"               \
        : "+f"((d)[0]), "+f"((d)[1]), "+f"((d)[2]), "+f"((d)[3])              \
        : "r"((a)[0]), "r"((a)[1]), "r"((a)[2]), "r"((a)[3]),                 \
          "r"((b)[0]), "r"((b)[1]))

#define LDSM4(r, addr)                                                        \
    asm volatile("ldmatrix.sync.aligned.m8n8.x4.shared.b16 "                  \
        "{%0,%1,%2,%3}, [%4];"                                                \
        : "=r"((r)[0]), "=r"((r)[1]), "=r"((r)[2]), "=r"((r)[3])              \
        : "r"(addr))

__device__ __forceinline__ void split_bf16(float v, bf16& h, bf16& l) {
    h = __float2bfloat16_rn(v);
    l = __float2bfloat16_rn(v - __bfloat162float(h));
}

// ---------------------------------------------------------------------------
// Prep kernel A (merged): biases/fcT + GEMM weight hi/lo planes
// ---------------------------------------------------------------------------
__global__ void k_wconv(const float* __restrict__ enc_b, const float* __restrict__ dec_b,
                        const float* __restrict__ fc_W,
                        const float* __restrict__ Wih0, const float* __restrict__ WihR,
                        float* __restrict__ encBP, float* __restrict__ decBP,
                        float* __restrict__ fcT,
                        bf16* __restrict__ W0H, bf16* __restrict__ W0L,
                        bf16* __restrict__ WRH, bf16* __restrict__ WRL) {
    int job = blockIdx.y;
    int i = blockIdx.x * 256 + threadIdx.x;
    if (job == 0) {
        if (i < 2048) {
            int l = i >> 9, n = i & 511;
            encBP[i] = enc_b[l * 512 + ((n & 3) * 128 + (n >> 2))];
        } else if (i < 4096) {
            int i2 = i - 2048;
            int l = i2 >> 9, n = i2 & 511;
            decBP[i2] = dec_b[l * 512 + ((n & 3) * 128 + (n >> 2))];
        } else if (i < 4096 + H * IN_DIM) {
            int i2 = i - 4096;
            int k = i2 / IN_DIM, j = i2 - k * IN_DIM;
            fcT[i2] = fc_W[j * H + k];
        }
    } else if (job == 1) {
        if (i < 512 * 48) {
            int n = i / 48, k = i - n * 48;
            float w = 0.f;
            if (k < IN_DIM) w = Wih0[((n & 3) * 128 + (n >> 2)) * IN_DIM + k];
            split_bf16(w, W0H[i], W0L[i]);
        }
    } else {
        int r = job - 2;
        if (i < 512 * 128) {
            int n = i >> 7, k = i & 127;
            float w = WihR[(long)r * 512 * 128 + ((n & 3) * 128 + (n >> 2)) * 128 + k];
            split_bf16(w, WRH[(long)r * 512 * 128 + i], WRL[(long)r * 512 * 128 + i]);
        }
    }
}

// ---------------------------------------------------------------------------
// Prep kernel B: gather x -> hi/lo bf16 [row][48]
// ---------------------------------------------------------------------------
__global__ void k_xconv(const float* __restrict__ x,
                        bf16* __restrict__ XH, bf16* __restrict__ XL) {
    for (long i = (long)blockIdx.x * 256 + threadIdx.x; i < (long)NROWS * 48;
         i += (long)gridDim.x * 256) {
        int row = (int)(i / 48), k = (int)(i - (long)row * 48);
        int t = row >> 11, b = row & 2047;
        float v = (k < IN_DIM) ? x[((long)b * SEQ + t) * IN_DIM + k] : 0.f;
        split_bf16(v, XH[i], XL[i]);
    }
}

// ---------------------------------------------------------------------------
// Prep kernel C: generalized fragment builder.
// ---------------------------------------------------------------------------
struct FJob { const float* s; ull* fh; ull* fl; int ksteps; int ksrc; };
struct FJobs { FJob j[12]; int n; };

__global__ void k_fragb(FJobs jobs) {
    int job = blockIdx.y;
    if (job >= jobs.n) return;
    FJob J = jobs.j[job];
    int e = blockIdx.x * 256 + threadIdx.x;
    int tot = 64 * J.ksteps * 32 * 2;
    if (e >= tot) return;
    int fi = e >> 1, jj = e & 1;
    int lane = fi & 31;
    int rest = fi >> 5;
    int s = rest % J.ksteps;
    int T = rest / J.ksteps;
    int n = T * 8 + (lane >> 2);
    int k = s * 16 + (lane & 3) * 2 + jj * 8;
    int row = (n & 3) * 128 + (n >> 2);
    float v0 = (k < J.ksrc) ? J.s[(long)row * J.ksrc + k] : 0.f;
    float v1 = (k + 1 < J.ksrc) ? J.s[(long)row * J.ksrc + k + 1] : 0.f;
    bf16 h0, l0, h1, l1;
    split_bf16(v0, h0, l0);
    split_bf16(v1, h1, l1);
    __nv_bfloat162 ph; ph.x = h0; ph.y = h1;
    __nv_bfloat162 pl; pl.x = l0; pl.y = l1;
    ((uint32_t*)J.fh)[e] = *(uint32_t*)&ph;
    ((uint32_t*)J.fl)[e] = *(uint32_t*)&pl;
}

// ---------------------------------------------------------------------------
// Persistent weight-resident split-bf16 tensor-core GEMM (unchanged)
// ---------------------------------------------------------------------------
template <int K>
__global__ void __launch_bounds__(512, 1)
k_mmagemm(const bf16* __restrict__ AH, const bf16* __restrict__ AL,
          const bf16* __restrict__ WH, const bf16* __restrict__ WL,
          const float* __restrict__ biasP, float* __restrict__ out) {
    extern __shared__ char smc[];
    const int KSTEPS = K / 16;
    const int ROWB = (K + 8) * 2;
    const int BSP  = 256 * ROWB;
    const int ASP2 = 64 * ROWB;
    const int CPR  = K / 8;

    char* Bb = smc;
    char* Ab = smc + 2 * BSP;
    float* bias_s = (float*)(smc + 2 * BSP + 4 * ASP2);

    const int tid = threadIdx.x;
    const int n0 = blockIdx.y * 256;
    const int w = tid >> 5, lane = tid & 31;
    const int wm = w >> 3, wn = w & 7;
    const int ar = lane >> 2, ac = (lane & 3) * 2;
    const int li = lane & 7, lq = lane >> 3;
    const int aoff = (li + (lq & 1) * 8) * ROWB + (lq >> 1) * 16;
    const int boff = (li + (lq >> 1) * 8) * ROWB + (lq & 1) * 16;

    const unsigned Bb_s = (unsigned)__cvta_generic_to_shared(Bb);
    const unsigned Ab_s = (unsigned)__cvta_generic_to_shared(Ab);

    if (tid < 256) bias_s[tid] = biasP[n0 + tid];

    {
        const int total = 2 * 256 * CPR;
        for (int i = tid; i < total; i += 512) {
            int split = i / (256 * CPR);
            int rem = i - split * 256 * CPR;
            int n = rem / CPR, ch = rem - n * CPR;
            const bf16* src = (split ? WL : WH) + (long)(n0 + n) * K + ch * 8;
            unsigned dst = (unsigned)__cvta_generic_to_shared(
                Bb + split * BSP + n * ROWB + ch * 16);
            cp16(dst, src);
        }
        cp_commit();
    }

    auto issueA = [&](int mt, int buf) {
        const int total = 2 * 64 * CPR;
        for (int i = tid; i < total; i += 512) {
            int split = i / (64 * CPR);
            int rem = i - split * 64 * CPR;
            int row = rem / CPR, ch = rem - row * CPR;
            const bf16* src = (split ? AL : AH) + (long)(mt * 64 + row) * K + ch * 8;
            unsigned dst = (unsigned)__cvta_generic_to_shared(
                Ab + buf * 2 * ASP2 + split * ASP2 + row * ROWB + ch * 16);
            cp16(dst, src);
        }
        cp_commit();
    };

    issueA(blockIdx.x, 0);
    cp_wait0();
    __syncthreads();

    int it = 0;
    for (int mt = blockIdx.x; mt < MT64; mt += GBX, ++it) {
        const int buf = it & 1;
        const bool more = (mt + GBX < MT64);
        if (more) issueA(mt + GBX, buf ^ 1);

        const unsigned Ahb = Ab_s + buf * 2 * ASP2;

        float acc[2][4][4];
#pragma unroll
        for (int mi = 0; mi < 2; ++mi)
#pragma unroll
            for (int ni = 0; ni < 4; ++ni)
#pragma unroll
                for (int q = 0; q < 4; ++q) acc[mi][ni][q] = 0.f;

#pragma unroll
        for (int ks = 0; ks < KSTEPS; ++ks) {
            const int kb2 = ks * 32;
            uint32_t ah[2][4], al[2][4];
#pragma unroll
            for (int mi = 0; mi < 2; ++mi) {
                unsigned base = Ahb + (wm * 32 + mi * 16) * ROWB + kb2 + aoff;
                LDSM4(ah[mi], base);
                LDSM4(al[mi], base + ASP2);
            }
            uint32_t bhf[2][4], blf[2][4];
#pragma unroll
            for (int p = 0; p < 2; ++p) {
                unsigned nb = Bb_s + (wn * 32 + p * 16) * ROWB + kb2 + boff;
                LDSM4(bhf[p], nb);
                LDSM4(blf[p], nb + BSP);
            }
#pragma unroll
            for (int p = 0; p < 2; ++p) {
#pragma unroll
                for (int hh = 0; hh < 2; ++hh) {
                    int ni = p * 2 + hh;
                    uint32_t* bH = &bhf[p][hh * 2];
                    uint32_t* bL = &blf[p][hh * 2];
                    MMA_BF16(acc[0][ni], ah[0], bH);
                    MMA_BF16(acc[1][ni], ah[1], bH);
                    MMA_BF16(acc[0][ni], ah[0], bL);
                    MMA_BF16(acc[1][ni], ah[1], bL);
                    MMA_BF16(acc[0][ni], al[0], bH);
                    MMA_BF16(acc[1][ni], al[1], bH);
                }
            }
        }

        const int m0 = mt * 64;
#pragma unroll
        for (int mi = 0; mi < 2; ++mi) {
            int r = m0 + wm * 32 + mi * 16 + ar;
#pragma unroll
            for (int ni = 0; ni < 4; ++ni) {
                int cl = wn * 32 + ni * 8 + ac;
                float b0 = bias_s[cl], b1 = bias_s[cl + 1];
                float2 v0 = { acc[mi][ni][0] + b0, acc[mi][ni][1] + b1 };
                float2 v1 = { acc[mi][ni][2] + b0, acc[mi][ni][3] + b1 };
                *(float2*)&out[(long)r * H4 + n0 + cl] = v0;
                *(float2*)&out[(long)(r + 8) * H4 + n0 + cl] = v1;
            }
        }
        if (more) { cp_wait0(); __syncthreads(); }
    }
}

// ---------------------------------------------------------------------------
// Tensor-core encoder recurrence. R15: FL (lo-weight frags) live entirely in
// REGISTERS (64 ull per lane, loaded once) — removes the 128 KB/block/step L2
// stream. Xg prefetch via per-thread-owned cp.async chunks into a single smem
// buffer (each thread reads back exactly the 16B chunks it copied — no extra
// barrier needed).
// ---------------------------------------------------------------------------
#define AROWB 272
#define ASPL  (16 * AROWB)
#define BFRAG_BYTES 131072
#define GST   520
#define XROW  520
#define LSTM_MMA_SMEM (BFRAG_BYTES + 4 * ASPL + 16 * GST * 4 + 16 * XROW * 4)

template <bool WRITE_YS>
__global__ void __launch_bounds__(256, 1)
k_lstm_mma(const ull* __restrict__ FH, const ull* __restrict__ FL,
           bf16* __restrict__ ysH, bf16* __restrict__ ysL,
           float* __restrict__ hfin, float* __restrict__ cfin) {
    extern __shared__ char smc[];
    ull* BhF = (ull*)smc;
    char* As = smc + BFRAG_BYTES;
    float* gates = (float*)(As + 4 * ASPL);
    float* xgb = gates + 16 * GST;

    const int tid = threadIdx.x;
    const int w = tid >> 5, lane = tid & 31;
    const int li = lane & 7, lq = lane >> 3;
    const int aoff = (li + (lq & 1) * 8) * AROWB + (lq >> 1) * 16;
    const int ar = lane >> 2, ac = (lane & 3) * 2;
    const int cc = w * 16 + (lane & 15);
    const int hb = lane >> 4;
    const int b0 = blockIdx.x * TBU;

    // FL -> registers (64 ull per lane, whole-kernel lifetime)
    ull flr[64];
#pragma unroll
    for (int i = 0; i < 64; ++i)
        flr[i] = FL[((w * 8 + (i >> 3)) * 8 + (i & 7)) * 32 + lane];

    for (int i = tid; i < 16384; i += 256) BhF[i] = FH[i];
    for (int i = tid; i < 2 * ASPL / 4; i += 256) ((float*)As)[i] = 0.f;

    float c_reg[8], hlast[8];
    int gbc[8]; bool vld[8];
#pragma unroll
    for (int i = 0; i < 8; ++i) {
        c_reg[i] = 0.f; hlast[i] = 0.f;
        int b = hb * 8 + i;
        int gb = b0 + b;
        gbc[i] = gb < BATCH ? gb : BATCH - 1;
        vld[i] = (b < TBU) && (gb < BATCH);
    }

    // prefetch Xg(0): per-thread-owned chunks (b = hb*8+i, col 4cc)
    {
        const float* xg0 = g_Xg + 4 * cc;
#pragma unroll
        for (int i = 0; i < 8; ++i) {
            unsigned dst = (unsigned)__cvta_generic_to_shared(
                &xgb[(hb * 8 + i) * XROW + 4 * cc]);
            cp16(dst, xg0 + (long)gbc[i] * H4);
        }
        cp_commit();
        cp_wait0();
    }
    __syncthreads();

    const unsigned As_s = (unsigned)__cvta_generic_to_shared(As);

    for (int t = 0; t < SEQ; ++t) {
        const unsigned Ab = As_s + (t & 1) * (2 * ASPL);
        float acc[8][4];
#pragma unroll
        for (int ni = 0; ni < 8; ++ni)
#pragma unroll
            for (int q = 0; q < 4; ++q) acc[ni][q] = 0.f;

#pragma unroll
        for (int s = 0; s < 8; ++s) {
            uint32_t ah[4], al[4];
            LDSM4(ah, Ab + s * 32 + aoff);
            LDSM4(al, Ab + ASPL + s * 32 + aoff);
#pragma unroll
            for (int ni = 0; ni < 8; ++ni) {
                int fi = ((w * 8 + ni) * 8 + s) * 32 + lane;
                ull bh8 = BhF[fi];
                ull bl8 = flr[ni * 8 + s];
                uint32_t bh[2] = { (uint32_t)bh8, (uint32_t)(bh8 >> 32) };
                uint32_t bl[2] = { (uint32_t)bl8, (uint32_t)(bl8 >> 32) };
                MMA_BF16(acc[ni], ah, bh);
                MMA_BF16(acc[ni], ah, bl);
                MMA_BF16(acc[ni], al, bh);
            }
        }
#pragma unroll
        for (int ni = 0; ni < 8; ++ni) {
            int n0 = w * 64 + ni * 8 + ac;
            float2 v0 = { acc[ni][0], acc[ni][1] };
            float2 v1 = { acc[ni][2], acc[ni][3] };
            *(float2*)&gates[ar * GST + n0] = v0;
            *(float2*)&gates[(ar + 8) * GST + n0] = v1;
        }
        __syncwarp();
        cp_wait0();              // own Xg chunks for step t are complete
        char* An = As + (((t + 1) & 1)) * (2 * ASPL);
#pragma unroll
        for (int i = 0; i < 8; ++i) {
            int b = hb * 8 + i;
            float4 g4 = *(const float4*)&gates[b * GST + 4 * cc];
            float4 x4 = *(const float4*)&xgb[b * XROW + 4 * cc];
            float gi = g4.x + x4.x, gf = g4.y + x4.y;
            float gg = g4.z + x4.z, go = g4.w + x4.w;
            float cn = sigf(gf) * c_reg[i] + sigf(gi) * tanha(gg);
            c_reg[i] = cn;
            float hn = sigf(go) * tanha(cn);
            hlast[i] = hn;
            bf16 hh, hl;
            split_bf16(hn, hh, hl);
            *(bf16*)(An + b * AROWB + cc * 2) = hh;
            *(bf16*)(An + ASPL + b * AROWB + cc * 2) = hl;
            if (WRITE_YS && vld[i]) {
                long idx = ((long)t * BATCH + b0 + b) * H + cc;
                ysH[idx] = hh;
                ysL[idx] = hl;
            }
        }
        // issue prefetch of Xg(t+1) into own chunks (only this thread reads them)
        if (t + 1 < SEQ) {
            const float* xgn = g_Xg + (long)(t + 1) * BATCH * H4 + 4 * cc;
#pragma unroll
            for (int i = 0; i < 8; ++i) {
                unsigned dst = (unsigned)__cvta_generic_to_shared(
                    &xgb[(hb * 8 + i) * XROW + 4 * cc]);
                cp16(dst, xgn + (long)gbc[i] * H4);
            }
            cp_commit();
        }
        __syncthreads();
    }
#pragma unroll
    for (int i = 0; i < 8; ++i) {
        if (vld[i]) {
            long gb = b0 + hb * 8 + i;
            hfin[gb * H + cc] = hlast[i];
            cfin[gb * H + cc] = c_reg[i];
        }
    }
}

// ---------------------------------------------------------------------------
// Tensor-core fused decoder (unchanged from R14)
// ---------------------------------------------------------------------------
#define DIROWB 112
#define DISPL  (16 * DIROWB)
#define DSMFCW (H * IN_DIM)

__global__ void __launch_bounds__(256, 1)
k_decoder_mma(const float* __restrict__ x, const float* __restrict__ fc_b,
              const ull* __restrict__ WhFH, const ull* __restrict__ WhFL,
              const ull* __restrict__ WiFH, const ull* __restrict__ WiFL,
              const ull* __restrict__ Wi0FH, const ull* __restrict__ Wi0FL,
              float* __restrict__ out) {
    extern __shared__ char smc[];
    char* hbuf = smc;
    char* dinb = smc + NL * 2 * ASPL;
    float* gates = (float*)(dinb + 2 * DISPL);
    float* fcH = gates + 16 * GST;
    float* fcw = fcH + 2048;
    float* fcb = fcw + DSMFCW;

    const int tid = threadIdx.x;
    const int w = tid >> 5, lane = tid & 31;
    const int li = lane & 7, lq = lane >> 3;
    const int aoff  = (li + (lq & 1) * 8) * AROWB + (lq >> 1) * 16;
    const int aoff2 = (li + (lq & 1) * 8) * DIROWB + (lq >> 1) * 16;
    const int ar = lane >> 2, ac = (lane & 3) * 2;
    const int cc = w * 16 + (lane & 15);
    const int hbi = lane >> 4;
    const int b0 = blockIdx.x * TBU;

    int gbc[8]; bool vld[8];
#pragma unroll
    for (int i = 0; i < 8; ++i) {
        int b = hbi * 8 + i;
        int gb = b0 + b;
        gbc[i] = gb < BATCH ? gb : BATCH - 1;
        vld[i] = (b < TBU) && (gb < BATCH);
    }
    float c_reg[NL][8];
#pragma unroll
    for (int l = 0; l < NL; ++l)
#pragma unroll
        for (int i = 0; i < 8; ++i) {
            c_reg[l][i] = g_c[((long)l * BATCH + gbc[i]) * H + cc];
            float hv = g_h[((long)l * BATCH + gbc[i]) * H + cc];
            bf16 hh, hl;
            split_bf16(hv, hh, hl);
            int b = hbi * 8 + i;
            char* hb = hbuf + l * 2 * ASPL;
            *(bf16*)(hb + b * AROWB + cc * 2) = hh;
            *(bf16*)(hb + ASPL + b * AROWB + cc * 2) = hl;
        }
    for (int i = tid; i < 16 * 48; i += 256) {
        int b = i / 48, j = i - b * 48;
        int gb = b0 + b; if (gb >= BATCH) gb = BATCH - 1;
        float v = (j < IN_DIM) ? x[((long)gb * SEQ + (SEQ - 1)) * IN_DIM + j] : 0.f;
        bf16 hh, hl;
        split_bf16(v, hh, hl);
        *(bf16*)(dinb + b * DIROWB + j * 2) = hh;
        *(bf16*)(dinb + DISPL + b * DIROWB + j * 2) = hl;
    }
    for (int i = tid; i < DSMFCW; i += 256) fcw[i] = g_fcT[i];
    for (int i = tid; i < IN_DIM; i += 256) fcb[i] = fc_b[i];

    float4 bias[NL];
#pragma unroll
    for (int l = 0; l < NL; ++l)
        bias[l] = *(const float4*)&g_decBP[l * H4 + 4 * cc];
    __syncthreads();

    const unsigned hb_s = (unsigned)__cvta_generic_to_shared(hbuf);
    const unsigned di_s = (unsigned)__cvta_generic_to_shared(dinb);

    for (int t = 0; t < TDEC; ++t) {
#pragma unroll 1
        for (int l = 0; l < NL; ++l) {
            float acc[8][4];
#pragma unroll
            for (int ni = 0; ni < 8; ++ni)
#pragma unroll
                for (int q = 0; q < 4; ++q) acc[ni][q] = 0.f;

            {
                const unsigned AbH = hb_s + l * 2 * ASPL;
                const ull* FH = WhFH + (long)l * 16384;
                const ull* FL = WhFL + (long)l * 16384;
#pragma unroll
                for (int s = 0; s < 8; ++s) {
                    uint32_t ah[4], al[4];
                    LDSM4(ah, AbH + s * 32 + aoff);
                    LDSM4(al, AbH + ASPL + s * 32 + aoff);
#pragma unroll
                    for (int ni = 0; ni < 8; ++ni) {
                        int fi = ((w * 8 + ni) * 8 + s) * 32 + lane;
                        ull bh8 = FH[fi];
                        ull bl8 = FL[fi];
                        uint32_t bh[2] = { (uint32_t)bh8, (uint32_t)(bh8 >> 32) };
                        uint32_t bl[2] = { (uint32_t)bl8, (uint32_t)(bl8 >> 32) };
                        MMA_BF16(acc[ni], ah, bh);
                        MMA_BF16(acc[ni], ah, bl);
                        MMA_BF16(acc[ni], al, bh);
                    }
                }
            }
            if (l == 0) {
#pragma unroll
                for (int s = 0; s < 3; ++s) {
                    uint32_t ah[4], al[4];
                    LDSM4(ah, di_s + s * 32 + aoff2);
                    LDSM4(al, di_s + DISPL + s * 32 + aoff2);
#pragma unroll
                    for (int ni = 0; ni < 8; ++ni) {
                        int fi = ((w * 8 + ni) * 3 + s) * 32 + lane;
                        ull bh8 = Wi0FH[fi];
                        ull bl8 = Wi0FL[fi];
                        uint32_t bh[2] = { (uint32_t)bh8, (uint32_t)(bh8 >> 32) };
                        uint32_t bl[2] = { (uint32_t)bl8, (uint32_t)(bl8 >> 32) };
                        MMA_BF16(acc[ni], ah, bh);
                        MMA_BF16(acc[ni], ah, bl);
                        MMA_BF16(acc[ni], al, bh);
                    }
                }
            } else {
                const unsigned AbH = hb_s + (l - 1) * 2 * ASPL;
                const ull* FH = WiFH + (long)(l - 1) * 16384;
                const ull* FL = WiFL + (long)(l - 1) * 16384;
#pragma unroll
                for (int s = 0; s < 8; ++s) {
                    uint32_t ah[4], al[4];
                    LDSM4(ah, AbH + s * 32 + aoff);
                    LDSM4(al, AbH + ASPL + s * 32 + aoff);
#pragma unroll
                    for (int ni = 0; ni < 8; ++ni) {
                        int fi = ((w * 8 + ni) * 8 + s) * 32 + lane;
                        ull bh8 = FH[fi];
                        ull bl8 = FL[fi];
                        uint32_t bh[2] = { (uint32_t)bh8, (uint32_t)(bh8 >> 32) };
                        uint32_t bl[2] = { (uint32_t)bl8, (uint32_t)(bl8 >> 32) };
                        MMA_BF16(acc[ni], ah, bh);
                        MMA_BF16(acc[ni], ah, bl);
                        MMA_BF16(acc[ni], al, bh);
                    }
                }
            }
#pragma unroll
            for (int ni = 0; ni < 8; ++ni) {
                int n0 = w * 64 + ni * 8 + ac;
                float2 v0 = { acc[ni][0], acc[ni][1] };
                float2 v1 = { acc[ni][2], acc[ni][3] };
                *(float2*)&gates[ar * GST + n0] = v0;
                *(float2*)&gates[(ar + 8) * GST + n0] = v1;
            }
            __syncwarp();
            char* hb = hbuf + l * 2 * ASPL;
#pragma unroll
            for (int i = 0; i < 8; ++i) {
                int b = hbi * 8 + i;
                float4 g4 = *(const float4*)&gates[b * GST + 4 * cc];
                float gi = g4.x + bias[l].x, gf = g4.y + bias[l].y;
                float gg = g4.z + bias[l].z, go = g4.w + bias[l].w;
                float cn = sigf(gf) * c_reg[l][i] + sigf(gi) * tanha(gg);
                c_reg[l][i] = cn;
                float hn = sigf(go) * tanha(cn);
                bf16 hh, hl;
                split_bf16(hn, hh, hl);
                *(bf16*)(hb + b * AROWB + cc * 2) = hh;
                *(bf16*)(hb + ASPL + b * AROWB + cc * 2) = hl;
                if (l == NL - 1) fcH[cc * 16 + b] = hn;
            }
            __syncthreads();
        }
        for (int idx = tid; idx < 16 * IN_DIM; idx += 256) {
            int b = idx / IN_DIM, j = idx - b * IN_DIM;
            float s = fcb[j];
#pragma unroll 8
            for (int k = 0; k < H; ++k)
                s += fcH[k * 16 + b] * fcw[k * IN_DIM + j];
            if (b < TBU && b0 + b < BATCH)
                out[((long)(b0 + b) * TDEC + t) * IN_DIM + j] = s;
            bf16 hh, hl;
            split_bf16(s, hh, hl);
            *(bf16*)(dinb + b * DIROWB + j * 2) = hh;
            *(bf16*)(dinb + DISPL + b * DIROWB + j * 2) = hl;
        }
        __syncthreads();
    }
}

// ---------------------------------------------------------------------------
// Host launcher
// ---------------------------------------------------------------------------
extern "C" void kernel_launch(void* const* d_in, const int* in_sizes, int n_in,
                              void* d_out, int out_size) {
    const float* x        = (const float*)d_in[0];
    const float* enc_Wih0 = (const float*)d_in[2];
    const float* enc_WihR = (const float*)d_in[3];
    const float* enc_Whh  = (const float*)d_in[4];
    const float* enc_b    = (const float*)d_in[5];
    const float* dec_Wih0 = (const float*)d_in[6];
    const float* dec_WihR = (const float*)d_in[7];
    const float* dec_Whh  = (const float*)d_in[8];
    const float* dec_b    = (const float*)d_in[9];
    const float* fc_W     = (const float*)d_in[10];
    const float* fc_b     = (const float*)d_in[11];
    float* out = (float*)d_out;

    float *encBP, *decBP, *fcT, *Xg, *hSt, *cSt;
    bf16 *W0H, *W0L, *WRH, *WRL, *ysH, *ysL, *x0H, *x0L;
    ull *eFH, *eFL, *dWhH, *dWhL, *dWiH, *dWiL, *dWi0H, *dWi0L;
    cudaGetSymbolAddress((void**)&encBP, g_encBP);
    cudaGetSymbolAddress((void**)&decBP, g_decBP);
    cudaGetSymbolAddress((void**)&fcT,   g_fcT);
    cudaGetSymbolAddress((void**)&Xg,    g_Xg);
    cudaGetSymbolAddress((void**)&hSt,   g_h);
    cudaGetSymbolAddress((void**)&cSt,   g_c);
    cudaGetSymbolAddress((void**)&W0H,   g_W0H);
    cudaGetSymbolAddress((void**)&W0L,   g_W0L);
    cudaGetSymbolAddress((void**)&WRH,   g_WRH);
    cudaGetSymbolAddress((void**)&WRL,   g_WRL);
    cudaGetSymbolAddress((void**)&ysH,   g_ysH);
    cudaGetSymbolAddress((void**)&ysL,   g_ysL);
    cudaGetSymbolAddress((void**)&x0H,   g_x0H);
    cudaGetSymbolAddress((void**)&x0L,   g_x0L);
    cudaGetSymbolAddress((void**)&eFH,   g_eWhFH);
    cudaGetSymbolAddress((void**)&eFL,   g_eWhFL);
    cudaGetSymbolAddress((void**)&dWhH,  g_dWhFH);
    cudaGetSymbolAddress((void**)&dWhL,  g_dWhFL);
    cudaGetSymbolAddress((void**)&dWiH,  g_dWiFH);
    cudaGetSymbolAddress((void**)&dWiL,  g_dWiFL);
    cudaGetSymbolAddress((void**)&dWi0H, g_dWi0FH);
    cudaGetSymbolAddress((void**)&dWi0L, g_dWi0FL);

    const int DYN48  = 2 * (256 * 112) + 4 * (64 * 112) + 1024;
    const int DYN128 = 2 * (256 * 272) + 4 * (64 * 272) + 1024;
    const int DECSM = NL * 2 * ASPL + 2 * DISPL + 16 * GST * 4 + 2048 * 4
                    + DSMFCW * 4 + 192;
    cudaFuncSetAttribute(k_mmagemm<48>,
                         cudaFuncAttributeMaxDynamicSharedMemorySize, DYN48);
    cudaFuncSetAttribute(k_mmagemm<128>,
                         cudaFuncAttributeMaxDynamicSharedMemorySize, DYN128);
    cudaFuncSetAttribute(k_lstm_mma<true>,
                         cudaFuncAttributeMaxDynamicSharedMemorySize, LSTM_MMA_SMEM);
    cudaFuncSetAttribute(k_lstm_mma<false>,
                         cudaFuncAttributeMaxDynamicSharedMemorySize, LSTM_MMA_SMEM);
    cudaFuncSetAttribute(k_decoder_mma,
                         cudaFuncAttributeMaxDynamicSharedMemorySize, DECSM);

    // prep (3 launches)
    {
        dim3 g(256, 5);
        k_wconv<<<g, 256>>>(enc_b, dec_b, fc_W, enc_Wih0, enc_WihR,
                            encBP, decBP, fcT, W0H, W0L, WRH, WRL);
    }
    {
        FJobs jf; jf.n = 12;
        for (int l = 0; l < NL; ++l)
            jf.j[l] = { enc_Whh + (long)l * 512 * 128, eFH + (long)l * 16384,
                        eFL + (long)l * 16384, 8, 128 };
        for (int l = 0; l < NL; ++l)
            jf.j[4 + l] = { dec_Whh + (long)l * 512 * 128, dWhH + (long)l * 16384,
                            dWhL + (long)l * 16384, 8, 128 };
        for (int r = 0; r < 3; ++r)
            jf.j[8 + r] = { dec_WihR + (long)r * 512 * 128, dWiH + (long)r * 16384,
                            dWiL + (long)r * 16384, 8, 128 };
        jf.j[11] = { dec_Wih0, dWi0H, dWi0L, 3, IN_DIM };
        dim3 g(128, 12);
        k_fragb<<<g, 256>>>(jf);
    }
    k_xconv<<<2048, 256>>>(x, x0H, x0L);

    dim3 ggrid(GBX, 2);

    // encoder layer 0
    k_mmagemm<48><<<ggrid, 512, DYN48>>>(x0H, x0L, W0H, W0L, encBP, Xg);
    k_lstm_mma<true><<<RBLK, 256, LSTM_MMA_SMEM>>>(eFH, eFL, ysH, ysL, hSt, cSt);
    // encoder layers 1..3
    for (int l = 1; l < NL; ++l) {
        k_mmagemm<128><<<ggrid, 512, DYN128>>>(
            ysH, ysL, WRH + (long)(l - 1) * 512 * 128, WRL + (long)(l - 1) * 512 * 128,
            encBP + (long)l * H4, Xg);
        if (l < NL - 1)
            k_lstm_mma<true><<<RBLK, 256, LSTM_MMA_SMEM>>>(
                eFH + (long)l * 16384, eFL + (long)l * 16384, ysH, ysL,
                hSt + (long)l * BATCH * H, cSt + (long)l * BATCH * H);
        else
            k_lstm_mma<false><<<RBLK, 256, LSTM_MMA_SMEM>>>(
                eFH + (long)l * 16384, eFL + (long)l * 16384, nullptr, nullptr,
                hSt + (long)l * BATCH * H, cSt + (long)l * BATCH * H);
    }
    // tensor-core fused decoder
    k_decoder_mma<<<RBLK, 256, DECSM>>>(x, fc_b, dWhH, dWhL, dWiH, dWiL,
                                        dWi0H, dWi0L, out);
}